// round 14
// baseline (speedup 1.0000x reference)
#include <cuda_runtime.h>
#include <cuda_fp16.h>
#include <cstdint>
#include <math.h>

#define BATCH 4
#define CCH   512
#define HCH   64
#define NPIX  4096
#define LOG2E 1.4426950408889634f

// ---------------- device scratch ----------------
__device__ __align__(16) __half g_fT[BATCH * NPIX * HCH];   // f^T [n][64], pre-scaled log2e
__device__ __align__(16) __half g_gT[BATCH * NPIX * HCH];   // g^T [n][64]
__device__ __align__(16) __half g_h [BATCH * HCH * NPIX];   // h   [64][n]
__device__ __align__(16) __half g_oT[BATCH * NPIX * HCH];   // o^T [n][64]
__device__ __align__(16) __half g_Wp[3 * HCH * CCH];        // W' fp16 (invsig, log2e folded)
__device__ __align__(16) __half g_Wvp[CCH * HCH];           // Wv' fp16 (invsig folded)
__device__ float g_invsig[4];

// ---------------- helpers (baseline PTX only) ----------------
__device__ __forceinline__ uint32_t smem_u32(const void* p) {
    uint32_t a;
    asm("{ .reg .u64 t; cvta.to.shared.u64 t, %1; cvt.u32.u64 %0, t; }" : "=r"(a) : "l"(p));
    return a;
}
__device__ __forceinline__ float ex2(float x) {
    float y; asm("ex2.approx.ftz.f32 %0, %1;" : "=f"(y) : "f"(x)); return y;
}
#define SW128(o) ((o) ^ (((o) >> 3) & 0x70))

__device__ __forceinline__ void cp_async16(uint32_t dst, const void* src) {
    asm volatile("cp.async.cg.shared.global [%0], [%1], 16;" :: "r"(dst), "l"(src) : "memory");
}
#define CP_COMMIT() asm volatile("cp.async.commit_group;" ::: "memory")
#define CP_WAIT(n)  asm volatile("cp.async.wait_group %0;" :: "n"(n) : "memory")

__device__ __forceinline__ void ldsm4(uint32_t* r, uint32_t a) {
    asm volatile("ldmatrix.sync.aligned.m8n8.x4.shared.b16 {%0,%1,%2,%3}, [%4];"
                 : "=r"(r[0]), "=r"(r[1]), "=r"(r[2]), "=r"(r[3]) : "r"(a));
}
__device__ __forceinline__ void mma16816(float* c, const uint32_t* a, const uint32_t* b) {
    asm volatile("mma.sync.aligned.m16n8k16.row.col.f32.f16.f16.f32 "
                 "{%0,%1,%2,%3}, {%4,%5,%6,%7}, {%8,%9}, {%0,%1,%2,%3};"
                 : "+f"(c[0]), "+f"(c[1]), "+f"(c[2]), "+f"(c[3])
                 : "r"(a[0]), "r"(a[1]), "r"(a[2]), "r"(a[3]), "r"(b[0]), "r"(b[1]));
}
__device__ __forceinline__ uint32_t pack_h2(__half a, __half b) {
    __half2 t = __halves2half2(a, b);
    return *reinterpret_cast<uint32_t*>(&t);
}
// copy rows x 128B tile (half source) into SW128-swizzled smem, 256 threads
__device__ __forceinline__ void cp_tile(uint32_t sbase, const __half* src,
                                        size_t rstride, int tid, int rows) {
    int total = rows * 8;
    for (int c = tid; c < total; c += 256) {
        int row = c >> 3, j = c & 7;
        cp_async16(sbase + SW128(row * 128 + j * 16), src + row * rstride + j * 8);
    }
}

// ---------------------------------------------------------------------------
// Spectral norm: sigma = || W @ normalize(W^T u) ||
// ---------------------------------------------------------------------------
__global__ void spectral_kernel(const float* __restrict__ Wf, const float* __restrict__ Wg,
                                const float* __restrict__ Wh, const float* __restrict__ Wv,
                                const float* __restrict__ uf, const float* __restrict__ ug,
                                const float* __restrict__ uh, const float* __restrict__ uv)
{
    __shared__ float u_s[512], v_s[512], red[512];
    int w = blockIdx.x;
    const float* W; const float* u; int R, Cc;
    if (w == 0)      { W = Wf; u = uf; R = HCH; Cc = CCH; }
    else if (w == 1) { W = Wg; u = ug; R = HCH; Cc = CCH; }
    else if (w == 2) { W = Wh; u = uh; R = HCH; Cc = CCH; }
    else             { W = Wv; u = uv; R = CCH; Cc = HCH; }
    int t = threadIdx.x;
    if (t < R) u_s[t] = u[t];
    __syncthreads();
    float v = 0.f;
    if (t < Cc) for (int r = 0; r < R; ++r) v += W[r * Cc + t] * u_s[r];
    red[t] = (t < Cc) ? v * v : 0.f;
    __syncthreads();
    for (int s = 256; s > 0; s >>= 1) { if (t < s) red[t] += red[t + s]; __syncthreads(); }
    float rn = rsqrtf(fmaxf(red[0], 1e-24f));
    if (t < Cc) v_s[t] = v * rn;
    __syncthreads();
    float tv = 0.f;
    if (t < R) { const float* row = W + t * Cc; for (int c = 0; c < Cc; ++c) tv += row[c] * v_s[c]; }
    red[t] = (t < R) ? tv * tv : 0.f;
    __syncthreads();
    for (int s = 256; s > 0; s >>= 1) { if (t < s) red[t] += red[t + s]; __syncthreads(); }
    if (t == 0) g_invsig[w] = rsqrtf(fmaxf(red[0], 1e-24f));
}

// ---------------------------------------------------------------------------
// Weight conversion: fold invsig (and log2e for Wf) into fp16 weights.
// ---------------------------------------------------------------------------
__global__ void wconv_kernel(const float* __restrict__ Wf, const float* __restrict__ Wg,
                             const float* __restrict__ Wh, const float* __restrict__ Wv)
{
    int idx = blockIdx.x * 256 + threadIdx.x;
    int stride = gridDim.x * 256;
    for (int i = idx; i < 3 * HCH * CCH + CCH * HCH; i += stride) {
        if (i < 3 * HCH * CCH) {
            int w = i / (HCH * CCH), r = i % (HCH * CCH);
            const float* W = (w == 0) ? Wf : ((w == 1) ? Wg : Wh);
            float scl = g_invsig[w] * (w == 0 ? LOG2E : 1.0f);
            g_Wp[i] = __float2half_rn(W[r] * scl);
        } else {
            int r = i - 3 * HCH * CCH;
            g_Wvp[r] = __float2half_rn(Wv[r] * g_invsig[3]);
        }
    }
}

// ---------------------------------------------------------------------------
// Fused MMA projections, ONE barrier per chunk (double-buffered xT).
// grid (32, 4), 256 threads.
// SMEM: xraw 2x32KB @0; xT 2x16KB @65536; W 3x24KB @98304; bias @172032.
// ---------------------------------------------------------------------------
#define PX_XRAW 0
#define PX_XT   65536
#define PX_W    98304
#define PX_BIAS 172032
#define SM_PROJ_TOT 172800

__device__ __forceinline__ void cp_xraw(uint32_t sb, int buf, const float* xb,
                                        int c, int n0, int tid) {
    for (int idx = tid; idx < 64 * 32; idx += 256) {
        int row = idx >> 5, jj = idx & 31;
        cp_async16(sb + PX_XRAW + buf * 32768 + row * 512 + ((jj ^ (row & 7)) << 4),
                   xb + (size_t)(c * 64 + row) * NPIX + n0 + jj * 4);
    }
}
__device__ __forceinline__ void cp_Wchunk(uint32_t sb, int buf, int c, int tid) {
#pragma unroll
    for (int w = 0; w < 3; ++w)
        cp_tile(sb + PX_W + buf * 24576 + w * 8192, g_Wp + w * 32768 + c * 64, 512, tid, 64);
}
// convert xraw[k&1] -> xT[k&1] fp16 swizzled (same mapping as round 6)
__device__ __forceinline__ void convert_chunk(char* smem, int k, int tid) {
    int ch = tid & 63, q4 = tid >> 6;
    const char* xr = smem + PX_XRAW + (k & 1) * 32768 + ch * 512;
    char* xt = smem + PX_XT + (k & 1) * 16384;
#pragma unroll
    for (int i = 0; i < 8; ++i) {
        int j = q4 * 8 + i;
        float4 v = *(const float4*)(xr + ((j ^ (ch & 7)) << 4));
        int p = j * 4;
        *(__half*)(xt + SW128((p + 0) * 128 + ch * 2)) = __float2half_rn(v.x);
        *(__half*)(xt + SW128((p + 1) * 128 + ch * 2)) = __float2half_rn(v.y);
        *(__half*)(xt + SW128((p + 2) * 128 + ch * 2)) = __float2half_rn(v.z);
        *(__half*)(xt + SW128((p + 3) * 128 + ch * 2)) = __float2half_rn(v.w);
    }
}

__global__ void __launch_bounds__(256, 1) proj_kernel(
    const float* __restrict__ x,
    const float* __restrict__ bf, const float* __restrict__ bg, const float* __restrict__ bh)
{
    extern __shared__ __align__(128) char smem[];
    int tid = threadIdx.x;
    int lane = tid & 31, wid = tid >> 5;
    int wpix0 = wid * 16;
    int nb = blockIdx.x, b = blockIdx.y;
    int n0 = nb * 128;
    uint32_t sb = smem_u32(smem);
    const float* xb = x + (size_t)b * CCH * NPIX;

    cp_xraw(sb, 0, xb, 0, n0, tid); cp_Wchunk(sb, 0, 0, tid); CP_COMMIT();
    cp_xraw(sb, 1, xb, 1, n0, tid); cp_Wchunk(sb, 1, 1, tid); CP_COMMIT();

    float* bias_s = (float*)(smem + PX_BIAS);
    if (tid < 192) {
        int w = tid >> 6, d = tid & 63;
        bias_s[tid] = (w == 0) ? bf[d] * LOG2E : ((w == 1) ? bg[d] : bh[d]);
    }

    float cf[8][4], cg[8][4], chh[4][2][4];
#pragma unroll
    for (int i = 0; i < 8; ++i)
#pragma unroll
        for (int j = 0; j < 4; ++j) { cf[i][j] = 0.f; cg[i][j] = 0.f; }
#pragma unroll
    for (int i = 0; i < 4; ++i)
#pragma unroll
        for (int n = 0; n < 2; ++n)
#pragma unroll
            for (int j = 0; j < 4; ++j) chh[i][n][j] = 0.f;

    int brow = lane & 7;
    int bj = lane >> 3;
    int bcol = (bj & 1) * 16 + (bj >> 1) * 32;
    int acolb = ((lane >> 4) & 1) * 16;

    // prologue: chunk 0 raw -> xT[0]
    CP_WAIT(1);
    __syncthreads();
    convert_chunk(smem, 0, tid);

    for (int c = 0; c < 8; ++c) {
        // 1. all outstanding groups done (chunk c+1 raw), publish smem stores
        CP_WAIT(0);
        __syncthreads();
        // 2. convert chunk c+1 into xT[(c+1)&1] (xT[c&1] untouched)
        if (c < 7) convert_chunk(smem, c + 1, tid);
        // 3. prefetch chunk c+2 (raw buf (c)&1 is free: chunk c converted last iter)
        if (c < 6) {
            cp_xraw(sb, c & 1, xb, c + 2, n0, tid);
            cp_Wchunk(sb, (c + 2) % 3, c + 2, tid);
            CP_COMMIT();
        }
        // 4. MMAs for chunk c from xT[c&1] (published by this iteration's bar);
        //    warps interleave leftover convert work with MMA issue — no barrier between.
        uint32_t xtb = sb + PX_XT + (c & 1) * 16384;
        uint32_t wtb = sb + PX_W + (c % 3) * 24576;
        uint32_t ax[4][4];
        int arow = wpix0 + (lane & 7) + ((lane >> 3) & 1) * 8;
#pragma unroll
        for (int kc = 0; kc < 4; ++kc)
            ldsm4(ax[kc], xtb + SW128(arow * 128 + kc * 32 + acolb));
        // f
#pragma unroll
        for (int nt = 0; nt < 8; ++nt) {
            uint32_t bw[8];
            uint32_t o0 = SW128((nt * 8 + brow) * 128 + bcol);
            uint32_t o1 = SW128((nt * 8 + brow) * 128 + 64 + bcol);
            ldsm4(bw, wtb + o0); ldsm4(bw + 4, wtb + o1);
#pragma unroll
            for (int kc = 0; kc < 4; ++kc) mma16816(cf[nt], ax[kc], &bw[kc * 2]);
        }
        // g
#pragma unroll
        for (int nt = 0; nt < 8; ++nt) {
            uint32_t bw[8];
            uint32_t o0 = SW128((nt * 8 + brow) * 128 + bcol);
            uint32_t o1 = SW128((nt * 8 + brow) * 128 + 64 + bcol);
            ldsm4(bw, wtb + 8192 + o0); ldsm4(bw + 4, wtb + 8192 + o1);
#pragma unroll
            for (int kc = 0; kc < 4; ++kc) mma16816(cg[nt], ax[kc], &bw[kc * 2]);
        }
        // h
        uint32_t bx[2][8];
#pragma unroll
        for (int nt = 0; nt < 2; ++nt) {
            uint32_t o0 = SW128((wpix0 + nt * 8 + brow) * 128 + bcol);
            uint32_t o1 = SW128((wpix0 + nt * 8 + brow) * 128 + 64 + bcol);
            ldsm4(bx[nt], xtb + o0); ldsm4(bx[nt] + 4, xtb + o1);
        }
#pragma unroll
        for (int mt = 0; mt < 4; ++mt) {
            uint32_t aw[4][4];
            int ar = mt * 16 + (lane & 7) + ((lane >> 3) & 1) * 8;
#pragma unroll
            for (int kc = 0; kc < 4; ++kc)
                ldsm4(aw[kc], wtb + 16384 + SW128(ar * 128 + kc * 32 + acolb));
#pragma unroll
            for (int nt = 0; nt < 2; ++nt)
#pragma unroll
                for (int kc = 0; kc < 4; ++kc)
                    mma16816(chh[mt][nt], aw[kc], &bx[nt][kc * 2]);
        }
    }

    // epilogue
    int q = wpix0 + (lane >> 2);
    size_t fbase = (size_t)b * NPIX * HCH + (size_t)(n0 + q) * HCH;
#pragma unroll
    for (int nt = 0; nt < 8; ++nt) {
        int d = nt * 8 + (lane & 3) * 2;
        float b0 = bias_s[d], b1 = bias_s[d + 1];
        *(uint32_t*)&g_fT[fbase + d] =
            pack_h2(__float2half_rn(cf[nt][0] + b0), __float2half_rn(cf[nt][1] + b1));
        *(uint32_t*)&g_fT[fbase + 8 * HCH + d] =
            pack_h2(__float2half_rn(cf[nt][2] + b0), __float2half_rn(cf[nt][3] + b1));
        float c0g = bias_s[64 + d], c1g = bias_s[64 + d + 1];
        *(uint32_t*)&g_gT[fbase + d] =
            pack_h2(__float2half_rn(cg[nt][0] + c0g), __float2half_rn(cg[nt][1] + c1g));
        *(uint32_t*)&g_gT[fbase + 8 * HCH + d] =
            pack_h2(__float2half_rn(cg[nt][2] + c0g), __float2half_rn(cg[nt][3] + c1g));
    }
    __half* Hp = g_h + (size_t)b * HCH * NPIX;
#pragma unroll
    for (int mt = 0; mt < 4; ++mt) {
        int d0 = mt * 16 + (lane >> 2), d1 = d0 + 8;
        float bb0 = bias_s[128 + d0], bb1 = bias_s[128 + d1];
#pragma unroll
        for (int nt = 0; nt < 2; ++nt) {
            int pix = n0 + wpix0 + nt * 8 + (lane & 3) * 2;
            *(uint32_t*)&Hp[(size_t)d0 * NPIX + pix] =
                pack_h2(__float2half_rn(chh[mt][nt][0] + bb0), __float2half_rn(chh[mt][nt][1] + bb0));
            *(uint32_t*)&Hp[(size_t)d1 * NPIX + pix] =
                pack_h2(__float2half_rn(chh[mt][nt][2] + bb1), __float2half_rn(chh[mt][nt][3] + bb1));
        }
    }
}

// ---------------------------------------------------------------------------
// mma.sync (fp16) flash attention (measured-best round-6 structure, unchanged).
// grid (32, B), 256 threads (8 warps x 16 q).
// ---------------------------------------------------------------------------
#define SM_FH 0
#define SM_BUF 16384
#define SM_ATTN_TOT 49152

__global__ void __launch_bounds__(256, 1) attn_kernel()
{
    extern __shared__ __align__(128) char smem[];
    int tid = threadIdx.x;
    int lane = tid & 31, wid = tid >> 5;
    int m0 = wid * 16;
    int b = blockIdx.y, n0 = blockIdx.x * 128;
    uint32_t sb = smem_u32(smem);

    size_t bo = (size_t)b * NPIX * HCH;
    const __half* fT = g_fT + bo + (size_t)n0 * HCH;
    const __half* gT = g_gT + bo;
    const __half* hp = g_h + (size_t)b * HCH * NPIX;

    cp_tile(sb + SM_FH, fT, 64, tid, 128);
    cp_tile(sb + SM_BUF,        gT, 64, tid, 64);
    cp_tile(sb + SM_BUF + 8192, hp, NPIX, tid, 64);
    CP_COMMIT();
    cp_tile(sb + SM_BUF + 16384, gT + 64 * 64, 64, tid, 64);
    cp_tile(sb + SM_BUF + 24576, hp + 64, NPIX, tid, 64);
    CP_COMMIT();

    CP_WAIT(1);
    __syncthreads();

    uint32_t fa[4][4];
    {
        int arow = m0 + (lane & 7) + ((lane >> 3) & 1) * 8;
        int acol = ((lane >> 4) & 1) * 16;
#pragma unroll
        for (int kc = 0; kc < 4; ++kc)
            ldsm4(fa[kc], sb + SM_FH + SW128(arow * 128 + kc * 32 + acol));
    }

    float oaccv[32];
#pragma unroll
    for (int i = 0; i < 32; ++i) oaccv[i] = 0.f;
    float m0r = -1e30f, m1r = -1e30f, l0 = 0.f, l1 = 0.f;

    int brow = lane & 7;
    int bj = lane >> 3;
    int bcol = (bj & 1) * 16 + (bj >> 1) * 32;

    for (int kt = 0; kt < 64; ++kt) {
        if (kt > 0) { CP_WAIT(1); __syncthreads(); }
        uint32_t gB = sb + SM_BUF + (kt & 1) * 16384;
        uint32_t hB = gB + 8192;

        float s[32];
#pragma unroll
        for (int i = 0; i < 32; ++i) s[i] = 0.f;
#pragma unroll
        for (int nt = 0; nt < 8; ++nt) {
            uint32_t bfr[8];
            uint32_t o0 = SW128((nt * 8 + brow) * 128 + 0 + bcol);
            uint32_t o1 = SW128((nt * 8 + brow) * 128 + 64 + bcol);
            ldsm4(bfr,     gB + o0);
            ldsm4(bfr + 4, gB + o1);
            float* s4 = &s[nt * 4];
#pragma unroll
            for (int kc = 0; kc < 4; ++kc) mma16816(s4, fa[kc], &bfr[kc * 2]);
        }

        float mx0 = -1e30f, mx1 = -1e30f;
#pragma unroll
        for (int nt = 0; nt < 8; ++nt) {
            mx0 = fmaxf(mx0, fmaxf(s[nt * 4 + 0], s[nt * 4 + 1]));
            mx1 = fmaxf(mx1, fmaxf(s[nt * 4 + 2], s[nt * 4 + 3]));
        }
        mx0 = fmaxf(mx0, __shfl_xor_sync(0xffffffffu, mx0, 1));
        mx0 = fmaxf(mx0, __shfl_xor_sync(0xffffffffu, mx0, 2));
        mx1 = fmaxf(mx1, __shfl_xor_sync(0xffffffffu, mx1, 1));
        mx1 = fmaxf(mx1, __shfl_xor_sync(0xffffffffu, mx1, 2));
        float mn0 = fmaxf(m0r, mx0), mn1 = fmaxf(m1r, mx1);
        float c0 = ex2(m0r - mn0), c1 = ex2(m1r - mn1);
        m0r = mn0; m1r = mn1;
        float ls0 = 0.f, ls1 = 0.f;
#pragma unroll
        for (int nt = 0; nt < 8; ++nt) {
            float p0 = ex2(s[nt * 4 + 0] - mn0);
            float p1 = ex2(s[nt * 4 + 1] - mn0);
            float p2 = ex2(s[nt * 4 + 2] - mn1);
            float p3 = ex2(s[nt * 4 + 3] - mn1);
            s[nt * 4 + 0] = p0; s[nt * 4 + 1] = p1;
            s[nt * 4 + 2] = p2; s[nt * 4 + 3] = p3;
            ls0 += p0 + p1; ls1 += p2 + p3;
        }
        l0 = l0 * c0 + ls0;
        l1 = l1 * c1 + ls1;
#pragma unroll
        for (int nt = 0; nt < 8; ++nt) {
            oaccv[nt * 4 + 0] *= c0; oaccv[nt * 4 + 1] *= c0;
            oaccv[nt * 4 + 2] *= c1; oaccv[nt * 4 + 3] *= c1;
        }

        uint32_t pa[4][4];
#pragma unroll
        for (int j = 0; j < 4; ++j) {
            float* sa = &s[(2 * j) * 4];
            float* sc = &s[(2 * j + 1) * 4];
            pa[j][0] = pack_h2(__float2half_rn(sa[0]), __float2half_rn(sa[1]));
            pa[j][1] = pack_h2(__float2half_rn(sa[2]), __float2half_rn(sa[3]));
            pa[j][2] = pack_h2(__float2half_rn(sc[0]), __float2half_rn(sc[1]));
            pa[j][3] = pack_h2(__float2half_rn(sc[2]), __float2half_rn(sc[3]));
        }

#pragma unroll
        for (int nd = 0; nd < 8; ++nd) {
            uint32_t bfr[8];
            uint32_t o0 = SW128((nd * 8 + brow) * 128 + 0 + bcol);
            uint32_t o1 = SW128((nd * 8 + brow) * 128 + 64 + bcol);
            ldsm4(bfr,     hB + o0);
            ldsm4(bfr + 4, hB + o1);
            float* o4 = &oaccv[nd * 4];
#pragma unroll
            for (int j = 0; j < 4; ++j) mma16816(o4, pa[j], &bfr[j * 2]);
        }

        __syncthreads();
        if (kt < 62) {
            uint32_t bb = sb + SM_BUF + (kt & 1) * 16384;
            cp_tile(bb,        gT + (size_t)(kt + 2) * 64 * 64, 64, tid, 64);
            cp_tile(bb + 8192, hp + (kt + 2) * 64, NPIX, tid, 64);
            CP_COMMIT();
        }
    }

    // epilogue: write o^T fp16 [pix][64] directly from fragments
    l0 += __shfl_xor_sync(0xffffffffu, l0, 1);
    l0 += __shfl_xor_sync(0xffffffffu, l0, 2);
    l1 += __shfl_xor_sync(0xffffffffu, l1, 1);
    l1 += __shfl_xor_sync(0xffffffffu, l1, 2);
    float inv0 = 1.f / l0, inv1 = 1.f / l1;

    int q0 = m0 + (lane >> 2), q1 = q0 + 8;
    size_t r0 = (size_t)b * NPIX * HCH + (size_t)(n0 + q0) * HCH;
    size_t r1 = (size_t)b * NPIX * HCH + (size_t)(n0 + q1) * HCH;
#pragma unroll
    for (int nt = 0; nt < 8; ++nt) {
        int d = nt * 8 + (lane & 3) * 2;
        *(uint32_t*)&g_oT[r0 + d] = pack_h2(__float2half_rn(oaccv[nt * 4 + 0] * inv0),
                                            __float2half_rn(oaccv[nt * 4 + 1] * inv0));
        *(uint32_t*)&g_oT[r1 + d] = pack_h2(__float2half_rn(oaccv[nt * 4 + 2] * inv1),
                                            __float2half_rn(oaccv[nt * 4 + 3] * inv1));
    }
}

// ---------------------------------------------------------------------------
// MMA outproj: out = gamma*(Wv' @ o + bv) + x.  grid (32, 8, 4), 256 threads.
// ---------------------------------------------------------------------------
__global__ void __launch_bounds__(256) outproj_kernel(
    const float* __restrict__ x, const float* __restrict__ bv,
    const float* __restrict__ gamma, float* __restrict__ out)
{
    __shared__ __align__(1024) char osm[24576];   // Wv tile 8KB @0, oT tile 16KB @8192
    int tid = threadIdx.x;
    int lane = tid & 31, wid = tid >> 5;
    int wpix0 = wid * 16;
    int nb = blockIdx.x, ct = blockIdx.y, b = blockIdx.z;
    int n0 = nb * 128, c0 = ct * 64;
    uint32_t sb = smem_u32(osm);

    cp_tile(sb, g_Wvp + c0 * 64, 64, tid, 64);
    cp_tile(sb + 8192, g_oT + ((size_t)b * NPIX + n0) * 64, 64, tid, 128);
    CP_COMMIT();
    CP_WAIT(0);
    __syncthreads();

    int brow = lane & 7;
    int bj = lane >> 3;
    int bcol = (bj & 1) * 16 + (bj >> 1) * 32;
    int acolb = ((lane >> 4) & 1) * 16;

    float co[4][2][4];
#pragma unroll
    for (int i = 0; i < 4; ++i)
#pragma unroll
        for (int n = 0; n < 2; ++n)
#pragma unroll
            for (int j = 0; j < 4; ++j) co[i][n][j] = 0.f;

    uint32_t bx[2][8];
#pragma unroll
    for (int nt = 0; nt < 2; ++nt) {
        uint32_t o0 = SW128((wpix0 + nt * 8 + brow) * 128 + bcol);
        uint32_t o1 = SW128((wpix0 + nt * 8 + brow) * 128 + 64 + bcol);
        ldsm4(bx[nt], sb + 8192 + o0); ldsm4(bx[nt] + 4, sb + 8192 + o1);
    }
#pragma unroll
    for (int mt = 0; mt < 4; ++mt) {
        uint32_t aw[4][4];
        int ar = mt * 16 + (lane & 7) + ((lane >> 3) & 1) * 8;
#pragma unroll
        for (int kc = 0; kc < 4; ++kc)
            ldsm4(aw[kc], sb + SW128(ar * 128 + kc * 32 + acolb));
#pragma unroll
        for (int nt = 0; nt < 2; ++nt)
#pragma unroll
            for (int kc = 0; kc < 4; ++kc)
                mma16816(co[mt][nt], aw[kc], &bx[nt][kc * 2]);
    }

    float gm = gamma[0];
#pragma unroll
    for (int mt = 0; mt < 4; ++mt) {
        int cA = c0 + mt * 16 + (lane >> 2);
        int cB = cA + 8;
        float bA = bv[cA], bB = bv[cB];
#pragma unroll
        for (int nt = 0; nt < 2; ++nt) {
            int pix = n0 + wpix0 + nt * 8 + (lane & 3) * 2;
            size_t iA = ((size_t)b * CCH + cA) * NPIX + pix;
            size_t iB = ((size_t)b * CCH + cB) * NPIX + pix;
            float2 xA = *(const float2*)&x[iA];
            float2 xB = *(const float2*)&x[iB];
            float2 oA, oB;
            oA.x = gm * (co[mt][nt][0] + bA) + xA.x;
            oA.y = gm * (co[mt][nt][1] + bA) + xA.y;
            oB.x = gm * (co[mt][nt][2] + bB) + xB.x;
            oB.y = gm * (co[mt][nt][3] + bB) + xB.y;
            *(float2*)&out[iA] = oA;
            *(float2*)&out[iB] = oB;
        }
    }
}

// ---------------------------------------------------------------------------
extern "C" void kernel_launch(void* const* d_in, const int* in_sizes, int n_in,
                              void* d_out, int out_size)
{
    const float* x     = (const float*)d_in[0];
    const float* Wf    = (const float*)d_in[1];
    const float* bf    = (const float*)d_in[2];
    const float* Wg    = (const float*)d_in[3];
    const float* bg    = (const float*)d_in[4];
    const float* Wh    = (const float*)d_in[5];
    const float* bh    = (const float*)d_in[6];
    const float* Wv    = (const float*)d_in[7];
    const float* bv    = (const float*)d_in[8];
    const float* uf    = (const float*)d_in[9];
    const float* ug    = (const float*)d_in[10];
    const float* uh    = (const float*)d_in[11];
    const float* uv    = (const float*)d_in[12];
    const float* gamma = (const float*)d_in[13];
    float* out = (float*)d_out;

    cudaFuncSetAttribute(attn_kernel, cudaFuncAttributeMaxDynamicSharedMemorySize, SM_ATTN_TOT);
    cudaFuncSetAttribute(proj_kernel, cudaFuncAttributeMaxDynamicSharedMemorySize, SM_PROJ_TOT);

    spectral_kernel<<<4, 512>>>(Wf, Wg, Wh, Wv, uf, ug, uh, uv);
    wconv_kernel<<<128, 256>>>(Wf, Wg, Wh, Wv);
    proj_kernel<<<dim3(NPIX / 128, BATCH), 256, SM_PROJ_TOT>>>(x, bf, bg, bh);
    attn_kernel<<<dim3(NPIX / 128, BATCH), 256, SM_ATTN_TOT>>>();
    outproj_kernel<<<dim3(NPIX / 128, CCH / 64, BATCH), 256>>>(x, bv, gamma, out);
}

// round 15
// speedup vs baseline: 1.5485x; 1.5485x over previous
#include <cuda_runtime.h>
#include <cuda_fp16.h>
#include <cstdint>
#include <math.h>

#define BATCH 4
#define CCH   512
#define HCH   64
#define NPIX  4096
#define LOG2E 1.4426950408889634f

// ---------------- device scratch ----------------
__device__ __align__(16) __half g_fT[BATCH * NPIX * HCH];   // f^T [n][64], pre-scaled log2e
__device__ __align__(16) __half g_gT[BATCH * NPIX * HCH];   // g^T [n][64]
__device__ __align__(16) __half g_h [BATCH * HCH * NPIX];   // h   [64][n]
__device__ __align__(16) __half g_oT[BATCH * NPIX * HCH];   // o^T [n][64]
__device__ __align__(16) __half g_Wp[3 * HCH * CCH];        // W' fp16 (invsig, log2e folded)
__device__ __align__(16) __half g_Wvp[CCH * HCH];           // Wv' fp16 (invsig folded)
__device__ float g_invsig[4];

// ---------------- helpers (baseline PTX only) ----------------
__device__ __forceinline__ uint32_t smem_u32(const void* p) {
    uint32_t a;
    asm("{ .reg .u64 t; cvta.to.shared.u64 t, %1; cvt.u32.u64 %0, t; }" : "=r"(a) : "l"(p));
    return a;
}
__device__ __forceinline__ float ex2(float x) {
    float y; asm("ex2.approx.ftz.f32 %0, %1;" : "=f"(y) : "f"(x)); return y;
}
#define SW128(o) ((o) ^ (((o) >> 3) & 0x70))

__device__ __forceinline__ void cp_async16(uint32_t dst, const void* src) {
    asm volatile("cp.async.cg.shared.global [%0], [%1], 16;" :: "r"(dst), "l"(src) : "memory");
}
#define CP_COMMIT() asm volatile("cp.async.commit_group;" ::: "memory")
#define CP_WAIT(n)  asm volatile("cp.async.wait_group %0;" :: "n"(n) : "memory")

__device__ __forceinline__ void ldsm4(uint32_t* r, uint32_t a) {
    asm volatile("ldmatrix.sync.aligned.m8n8.x4.shared.b16 {%0,%1,%2,%3}, [%4];"
                 : "=r"(r[0]), "=r"(r[1]), "=r"(r[2]), "=r"(r[3]) : "r"(a));
}
__device__ __forceinline__ void mma16816(float* c, const uint32_t* a, const uint32_t* b) {
    asm volatile("mma.sync.aligned.m16n8k16.row.col.f32.f16.f16.f32 "
                 "{%0,%1,%2,%3}, {%4,%5,%6,%7}, {%8,%9}, {%0,%1,%2,%3};"
                 : "+f"(c[0]), "+f"(c[1]), "+f"(c[2]), "+f"(c[3])
                 : "r"(a[0]), "r"(a[1]), "r"(a[2]), "r"(a[3]), "r"(b[0]), "r"(b[1]));
}
__device__ __forceinline__ uint32_t pack_h2(__half a, __half b) {
    __half2 t = __halves2half2(a, b);
    return *reinterpret_cast<uint32_t*>(&t);
}
// copy rows x 128B tile (half source) into SW128-swizzled smem, 256 threads
__device__ __forceinline__ void cp_tile(uint32_t sbase, const __half* src,
                                        size_t rstride, int tid, int rows) {
    int total = rows * 8;
    for (int c = tid; c < total; c += 256) {
        int row = c >> 3, j = c & 7;
        cp_async16(sbase + SW128(row * 128 + j * 16), src + row * rstride + j * 8);
    }
}

// ---------------------------------------------------------------------------
// Spectral norm: sigma = || W @ normalize(W^T u) ||
// ---------------------------------------------------------------------------
__global__ void spectral_kernel(const float* __restrict__ Wf, const float* __restrict__ Wg,
                                const float* __restrict__ Wh, const float* __restrict__ Wv,
                                const float* __restrict__ uf, const float* __restrict__ ug,
                                const float* __restrict__ uh, const float* __restrict__ uv)
{
    __shared__ float u_s[512], v_s[512], red[512];
    int w = blockIdx.x;
    const float* W; const float* u; int R, Cc;
    if (w == 0)      { W = Wf; u = uf; R = HCH; Cc = CCH; }
    else if (w == 1) { W = Wg; u = ug; R = HCH; Cc = CCH; }
    else if (w == 2) { W = Wh; u = uh; R = HCH; Cc = CCH; }
    else             { W = Wv; u = uv; R = CCH; Cc = HCH; }
    int t = threadIdx.x;
    if (t < R) u_s[t] = u[t];
    __syncthreads();
    float v = 0.f;
    if (t < Cc) for (int r = 0; r < R; ++r) v += W[r * Cc + t] * u_s[r];
    red[t] = (t < Cc) ? v * v : 0.f;
    __syncthreads();
    for (int s = 256; s > 0; s >>= 1) { if (t < s) red[t] += red[t + s]; __syncthreads(); }
    float rn = rsqrtf(fmaxf(red[0], 1e-24f));
    if (t < Cc) v_s[t] = v * rn;
    __syncthreads();
    float tv = 0.f;
    if (t < R) { const float* row = W + t * Cc; for (int c = 0; c < Cc; ++c) tv += row[c] * v_s[c]; }
    red[t] = (t < R) ? tv * tv : 0.f;
    __syncthreads();
    for (int s = 256; s > 0; s >>= 1) { if (t < s) red[t] += red[t + s]; __syncthreads(); }
    if (t == 0) g_invsig[w] = rsqrtf(fmaxf(red[0], 1e-24f));
}

// ---------------------------------------------------------------------------
// Weight conversion: fold invsig (and log2e for Wf) into fp16 weights.
// ---------------------------------------------------------------------------
__global__ void wconv_kernel(const float* __restrict__ Wf, const float* __restrict__ Wg,
                             const float* __restrict__ Wh, const float* __restrict__ Wv)
{
    int idx = blockIdx.x * 256 + threadIdx.x;
    int stride = gridDim.x * 256;
    for (int i = idx; i < 3 * HCH * CCH + CCH * HCH; i += stride) {
        if (i < 3 * HCH * CCH) {
            int w = i / (HCH * CCH), r = i % (HCH * CCH);
            const float* W = (w == 0) ? Wf : ((w == 1) ? Wg : Wh);
            float scl = g_invsig[w] * (w == 0 ? LOG2E : 1.0f);
            g_Wp[i] = __float2half_rn(W[r] * scl);
        } else {
            int r = i - 3 * HCH * CCH;
            g_Wvp[r] = __float2half_rn(Wv[r] * g_invsig[3]);
        }
    }
}

// ---------------------------------------------------------------------------
// Fused MMA projections: one CTA = [128 pix] x one batch; computes f,g,h.
// fT/gT written [pix][64]; h written [64][pix].  grid (32, 4), 256 threads.
// ---------------------------------------------------------------------------
#define PX_XRAW 0
#define PX_XT   65536
#define PX_W    81920
#define PX_BIAS 155648
#define SM_PROJ_TOT 156416

__device__ __forceinline__ void cp_xraw(uint32_t sb, int buf, const float* xb,
                                        int c, int n0, int tid) {
    for (int idx = tid; idx < 64 * 32; idx += 256) {
        int row = idx >> 5, jj = idx & 31;
        cp_async16(sb + PX_XRAW + buf * 32768 + row * 512 + ((jj ^ (row & 7)) << 4),
                   xb + (size_t)(c * 64 + row) * NPIX + n0 + jj * 4);
    }
}
__device__ __forceinline__ void cp_Wchunk(uint32_t sb, int buf, int c, int tid) {
#pragma unroll
    for (int w = 0; w < 3; ++w)
        cp_tile(sb + PX_W + buf * 24576 + w * 8192, g_Wp + w * 32768 + c * 64, 512, tid, 64);
}

__global__ void __launch_bounds__(256, 1) proj_kernel(
    const float* __restrict__ x,
    const float* __restrict__ bf, const float* __restrict__ bg, const float* __restrict__ bh)
{
    extern __shared__ __align__(128) char smem[];
    int tid = threadIdx.x;
    int lane = tid & 31, wid = tid >> 5;
    int wpix0 = wid * 16;
    int nb = blockIdx.x, b = blockIdx.y;
    int n0 = nb * 128;
    uint32_t sb = smem_u32(smem);
    const float* xb = x + (size_t)b * CCH * NPIX;

    cp_xraw(sb, 0, xb, 0, n0, tid); cp_Wchunk(sb, 0, 0, tid); CP_COMMIT();
    cp_xraw(sb, 1, xb, 1, n0, tid); cp_Wchunk(sb, 1, 1, tid); CP_COMMIT();

    float* bias_s = (float*)(smem + PX_BIAS);
    if (tid < 192) {
        int w = tid >> 6, d = tid & 63;
        bias_s[tid] = (w == 0) ? bf[d] * LOG2E : ((w == 1) ? bg[d] : bh[d]);
    }

    float cf[8][4], cg[8][4], chh[4][2][4];
#pragma unroll
    for (int i = 0; i < 8; ++i)
#pragma unroll
        for (int j = 0; j < 4; ++j) { cf[i][j] = 0.f; cg[i][j] = 0.f; }
#pragma unroll
    for (int i = 0; i < 4; ++i)
#pragma unroll
        for (int n = 0; n < 2; ++n)
#pragma unroll
            for (int j = 0; j < 4; ++j) chh[i][n][j] = 0.f;

    int brow = lane & 7;
    int bj = lane >> 3;
    int bcol = (bj & 1) * 16 + (bj >> 1) * 32;
    int acolb = ((lane >> 4) & 1) * 16;

    for (int c = 0; c < 8; ++c) {
        CP_WAIT(1);
        __syncthreads();
        // convert xraw[c&1] -> xT [pix][64] fp16 swizzled
        {
            int ch = tid & 63, q4 = tid >> 6;
            const char* xr = smem + PX_XRAW + (c & 1) * 32768 + ch * 512;
#pragma unroll
            for (int i = 0; i < 8; ++i) {
                int j = q4 * 8 + i;
                float4 v = *(const float4*)(xr + ((j ^ (ch & 7)) << 4));
                int p = j * 4;
                *(__half*)(smem + PX_XT + SW128((p + 0) * 128 + ch * 2)) = __float2half_rn(v.x);
                *(__half*)(smem + PX_XT + SW128((p + 1) * 128 + ch * 2)) = __float2half_rn(v.y);
                *(__half*)(smem + PX_XT + SW128((p + 2) * 128 + ch * 2)) = __float2half_rn(v.z);
                *(__half*)(smem + PX_XT + SW128((p + 3) * 128 + ch * 2)) = __float2half_rn(v.w);
            }
        }
        __syncthreads();
        if (c < 6) {
            cp_xraw(sb, c & 1, xb, c + 2, n0, tid);
            cp_Wchunk(sb, (c + 2) % 3, c + 2, tid);
            CP_COMMIT();
        }
        // MMA
        uint32_t xtb = sb + PX_XT;
        uint32_t wtb = sb + PX_W + (c % 3) * 24576;
        uint32_t ax[4][4];
        int arow = wpix0 + (lane & 7) + ((lane >> 3) & 1) * 8;
#pragma unroll
        for (int kc = 0; kc < 4; ++kc)
            ldsm4(ax[kc], xtb + SW128(arow * 128 + kc * 32 + acolb));
        // f
#pragma unroll
        for (int nt = 0; nt < 8; ++nt) {
            uint32_t bw[8];
            uint32_t o0 = SW128((nt * 8 + brow) * 128 + bcol);
            uint32_t o1 = SW128((nt * 8 + brow) * 128 + 64 + bcol);
            ldsm4(bw, wtb + o0); ldsm4(bw + 4, wtb + o1);
#pragma unroll
            for (int kc = 0; kc < 4; ++kc) mma16816(cf[nt], ax[kc], &bw[kc * 2]);
        }
        // g
#pragma unroll
        for (int nt = 0; nt < 8; ++nt) {
            uint32_t bw[8];
            uint32_t o0 = SW128((nt * 8 + brow) * 128 + bcol);
            uint32_t o1 = SW128((nt * 8 + brow) * 128 + 64 + bcol);
            ldsm4(bw, wtb + 8192 + o0); ldsm4(bw + 4, wtb + 8192 + o1);
#pragma unroll
            for (int kc = 0; kc < 4; ++kc) mma16816(cg[nt], ax[kc], &bw[kc * 2]);
        }
        // h
        uint32_t bx[2][8];
#pragma unroll
        for (int nt = 0; nt < 2; ++nt) {
            uint32_t o0 = SW128((wpix0 + nt * 8 + brow) * 128 + bcol);
            uint32_t o1 = SW128((wpix0 + nt * 8 + brow) * 128 + 64 + bcol);
            ldsm4(bx[nt], xtb + o0); ldsm4(bx[nt] + 4, xtb + o1);
        }
#pragma unroll
        for (int mt = 0; mt < 4; ++mt) {
            uint32_t aw[4][4];
            int ar = mt * 16 + (lane & 7) + ((lane >> 3) & 1) * 8;
#pragma unroll
            for (int kc = 0; kc < 4; ++kc)
                ldsm4(aw[kc], wtb + 16384 + SW128(ar * 128 + kc * 32 + acolb));
#pragma unroll
            for (int nt = 0; nt < 2; ++nt)
#pragma unroll
                for (int kc = 0; kc < 4; ++kc)
                    mma16816(chh[mt][nt], aw[kc], &bx[nt][kc * 2]);
        }
    }

    // epilogue
    int q = wpix0 + (lane >> 2);
    size_t fbase = (size_t)b * NPIX * HCH + (size_t)(n0 + q) * HCH;
#pragma unroll
    for (int nt = 0; nt < 8; ++nt) {
        int d = nt * 8 + (lane & 3) * 2;
        float b0 = bias_s[d], b1 = bias_s[d + 1];
        *(uint32_t*)&g_fT[fbase + d] =
            pack_h2(__float2half_rn(cf[nt][0] + b0), __float2half_rn(cf[nt][1] + b1));
        *(uint32_t*)&g_fT[fbase + 8 * HCH + d] =
            pack_h2(__float2half_rn(cf[nt][2] + b0), __float2half_rn(cf[nt][3] + b1));
        float c0g = bias_s[64 + d], c1g = bias_s[64 + d + 1];
        *(uint32_t*)&g_gT[fbase + d] =
            pack_h2(__float2half_rn(cg[nt][0] + c0g), __float2half_rn(cg[nt][1] + c1g));
        *(uint32_t*)&g_gT[fbase + 8 * HCH + d] =
            pack_h2(__float2half_rn(cg[nt][2] + c0g), __float2half_rn(cg[nt][3] + c1g));
    }
    __half* Hp = g_h + (size_t)b * HCH * NPIX;
#pragma unroll
    for (int mt = 0; mt < 4; ++mt) {
        int d0 = mt * 16 + (lane >> 2), d1 = d0 + 8;
        float bb0 = bias_s[128 + d0], bb1 = bias_s[128 + d1];
#pragma unroll
        for (int nt = 0; nt < 2; ++nt) {
            int pix = n0 + wpix0 + nt * 8 + (lane & 3) * 2;
            *(uint32_t*)&Hp[(size_t)d0 * NPIX + pix] =
                pack_h2(__float2half_rn(chh[mt][nt][0] + bb0), __float2half_rn(chh[mt][nt][1] + bb0));
            *(uint32_t*)&Hp[(size_t)d1 * NPIX + pix] =
                pack_h2(__float2half_rn(chh[mt][nt][2] + bb1), __float2half_rn(chh[mt][nt][3] + bb1));
        }
    }
}

// ---------------------------------------------------------------------------
// mma.sync (fp16) flash attention.  grid (32, B), 256 threads (8 warps x 16 q).
// ---------------------------------------------------------------------------
#define SM_FH 0
#define SM_BUF 16384
#define SM_ATTN_TOT 49152

__global__ void __launch_bounds__(256, 1) attn_kernel()
{
    extern __shared__ __align__(128) char smem[];
    int tid = threadIdx.x;
    int lane = tid & 31, wid = tid >> 5;
    int m0 = wid * 16;
    int b = blockIdx.y, n0 = blockIdx.x * 128;
    uint32_t sb = smem_u32(smem);

    size_t bo = (size_t)b * NPIX * HCH;
    const __half* fT = g_fT + bo + (size_t)n0 * HCH;
    const __half* gT = g_gT + bo;
    const __half* hp = g_h + (size_t)b * HCH * NPIX;

    cp_tile(sb + SM_FH, fT, 64, tid, 128);
    cp_tile(sb + SM_BUF,        gT, 64, tid, 64);
    cp_tile(sb + SM_BUF + 8192, hp, NPIX, tid, 64);
    CP_COMMIT();
    cp_tile(sb + SM_BUF + 16384, gT + 64 * 64, 64, tid, 64);
    cp_tile(sb + SM_BUF + 24576, hp + 64, NPIX, tid, 64);
    CP_COMMIT();

    CP_WAIT(1);
    __syncthreads();

    uint32_t fa[4][4];
    {
        int arow = m0 + (lane & 7) + ((lane >> 3) & 1) * 8;
        int acol = ((lane >> 4) & 1) * 16;
#pragma unroll
        for (int kc = 0; kc < 4; ++kc)
            ldsm4(fa[kc], sb + SM_FH + SW128(arow * 128 + kc * 32 + acol));
    }

    float oaccv[32];
#pragma unroll
    for (int i = 0; i < 32; ++i) oaccv[i] = 0.f;
    float m0r = -1e30f, m1r = -1e30f, l0 = 0.f, l1 = 0.f;

    int brow = lane & 7;
    int bj = lane >> 3;
    int bcol = (bj & 1) * 16 + (bj >> 1) * 32;

    for (int kt = 0; kt < 64; ++kt) {
        if (kt > 0) { CP_WAIT(1); __syncthreads(); }
        uint32_t gB = sb + SM_BUF + (kt & 1) * 16384;
        uint32_t hB = gB + 8192;

        float s[32];
#pragma unroll
        for (int i = 0; i < 32; ++i) s[i] = 0.f;
#pragma unroll
        for (int nt = 0; nt < 8; ++nt) {
            uint32_t bfr[8];
            uint32_t o0 = SW128((nt * 8 + brow) * 128 + 0 + bcol);
            uint32_t o1 = SW128((nt * 8 + brow) * 128 + 64 + bcol);
            ldsm4(bfr,     gB + o0);
            ldsm4(bfr + 4, gB + o1);
            float* s4 = &s[nt * 4];
#pragma unroll
            for (int kc = 0; kc < 4; ++kc) mma16816(s4, fa[kc], &bfr[kc * 2]);
        }

        float mx0 = -1e30f, mx1 = -1e30f;
#pragma unroll
        for (int nt = 0; nt < 8; ++nt) {
            mx0 = fmaxf(mx0, fmaxf(s[nt * 4 + 0], s[nt * 4 + 1]));
            mx1 = fmaxf(mx1, fmaxf(s[nt * 4 + 2], s[nt * 4 + 3]));
        }
        mx0 = fmaxf(mx0, __shfl_xor_sync(0xffffffffu, mx0, 1));
        mx0 = fmaxf(mx0, __shfl_xor_sync(0xffffffffu, mx0, 2));
        mx1 = fmaxf(mx1, __shfl_xor_sync(0xffffffffu, mx1, 1));
        mx1 = fmaxf(mx1, __shfl_xor_sync(0xffffffffu, mx1, 2));
        float mn0 = fmaxf(m0r, mx0), mn1 = fmaxf(m1r, mx1);
        float c0 = ex2(m0r - mn0), c1 = ex2(m1r - mn1);
        m0r = mn0; m1r = mn1;
        float ls0 = 0.f, ls1 = 0.f;
#pragma unroll
        for (int nt = 0; nt < 8; ++nt) {
            float p0 = ex2(s[nt * 4 + 0] - mn0);
            float p1 = ex2(s[nt * 4 + 1] - mn0);
            float p2 = ex2(s[nt * 4 + 2] - mn1);
            float p3 = ex2(s[nt * 4 + 3] - mn1);
            s[nt * 4 + 0] = p0; s[nt * 4 + 1] = p1;
            s[nt * 4 + 2] = p2; s[nt * 4 + 3] = p3;
            ls0 += p0 + p1; ls1 += p2 + p3;
        }
        l0 = l0 * c0 + ls0;
        l1 = l1 * c1 + ls1;
#pragma unroll
        for (int nt = 0; nt < 8; ++nt) {
            oaccv[nt * 4 + 0] *= c0; oaccv[nt * 4 + 1] *= c0;
            oaccv[nt * 4 + 2] *= c1; oaccv[nt * 4 + 3] *= c1;
        }

        uint32_t pa[4][4];
#pragma unroll
        for (int j = 0; j < 4; ++j) {
            float* sa = &s[(2 * j) * 4];
            float* sc = &s[(2 * j + 1) * 4];
            pa[j][0] = pack_h2(__float2half_rn(sa[0]), __float2half_rn(sa[1]));
            pa[j][1] = pack_h2(__float2half_rn(sa[2]), __float2half_rn(sa[3]));
            pa[j][2] = pack_h2(__float2half_rn(sc[0]), __float2half_rn(sc[1]));
            pa[j][3] = pack_h2(__float2half_rn(sc[2]), __float2half_rn(sc[3]));
        }

#pragma unroll
        for (int nd = 0; nd < 8; ++nd) {
            uint32_t bfr[8];
            uint32_t o0 = SW128((nd * 8 + brow) * 128 + 0 + bcol);
            uint32_t o1 = SW128((nd * 8 + brow) * 128 + 64 + bcol);
            ldsm4(bfr,     hB + o0);
            ldsm4(bfr + 4, hB + o1);
            float* o4 = &oaccv[nd * 4];
#pragma unroll
            for (int j = 0; j < 4; ++j) mma16816(o4, pa[j], &bfr[j * 2]);
        }

        __syncthreads();
        if (kt < 62) {
            uint32_t bb = sb + SM_BUF + (kt & 1) * 16384;
            cp_tile(bb,        gT + (size_t)(kt + 2) * 64 * 64, 64, tid, 64);
            cp_tile(bb + 8192, hp + (kt + 2) * 64, NPIX, tid, 64);
            CP_COMMIT();
        }
    }

    // epilogue: write o^T fp16 [pix][64] directly from fragments
    l0 += __shfl_xor_sync(0xffffffffu, l0, 1);
    l0 += __shfl_xor_sync(0xffffffffu, l0, 2);
    l1 += __shfl_xor_sync(0xffffffffu, l1, 1);
    l1 += __shfl_xor_sync(0xffffffffu, l1, 2);
    float inv0 = 1.f / l0, inv1 = 1.f / l1;

    int q0 = m0 + (lane >> 2), q1 = q0 + 8;
    size_t r0 = (size_t)b * NPIX * HCH + (size_t)(n0 + q0) * HCH;
    size_t r1 = (size_t)b * NPIX * HCH + (size_t)(n0 + q1) * HCH;
#pragma unroll
    for (int nt = 0; nt < 8; ++nt) {
        int d = nt * 8 + (lane & 3) * 2;
        *(uint32_t*)&g_oT[r0 + d] = pack_h2(__float2half_rn(oaccv[nt * 4 + 0] * inv0),
                                            __float2half_rn(oaccv[nt * 4 + 1] * inv0));
        *(uint32_t*)&g_oT[r1 + d] = pack_h2(__float2half_rn(oaccv[nt * 4 + 2] * inv1),
                                            __float2half_rn(oaccv[nt * 4 + 3] * inv1));
    }
}

// ---------------------------------------------------------------------------
// MMA outproj: out = gamma*(Wv' @ o + bv) + x.  grid (32, 8, 4), 256 threads.
// ---------------------------------------------------------------------------
__global__ void __launch_bounds__(256) outproj_kernel(
    const float* __restrict__ x, const float* __restrict__ bv,
    const float* __restrict__ gamma, float* __restrict__ out)
{
    __shared__ __align__(1024) char osm[24576];   // Wv tile 8KB @0, oT tile 16KB @8192
    int tid = threadIdx.x;
    int lane = tid & 31, wid = tid >> 5;
    int wpix0 = wid * 16;
    int nb = blockIdx.x, ct = blockIdx.y, b = blockIdx.z;
    int n0 = nb * 128, c0 = ct * 64;
    uint32_t sb = smem_u32(osm);

    cp_tile(sb, g_Wvp + c0 * 64, 64, tid, 64);
    cp_tile(sb + 8192, g_oT + ((size_t)b * NPIX + n0) * 64, 64, tid, 128);
    CP_COMMIT();
    CP_WAIT(0);
    __syncthreads();

    int brow = lane & 7;
    int bj = lane >> 3;
    int bcol = (bj & 1) * 16 + (bj >> 1) * 32;
    int acolb = ((lane >> 4) & 1) * 16;

    float co[4][2][4];
#pragma unroll
    for (int i = 0; i < 4; ++i)
#pragma unroll
        for (int n = 0; n < 2; ++n)
#pragma unroll
            for (int j = 0; j < 4; ++j) co[i][n][j] = 0.f;

    uint32_t bx[2][8];
#pragma unroll
    for (int nt = 0; nt < 2; ++nt) {
        uint32_t o0 = SW128((wpix0 + nt * 8 + brow) * 128 + bcol);
        uint32_t o1 = SW128((wpix0 + nt * 8 + brow) * 128 + 64 + bcol);
        ldsm4(bx[nt], sb + 8192 + o0); ldsm4(bx[nt] + 4, sb + 8192 + o1);
    }
#pragma unroll
    for (int mt = 0; mt < 4; ++mt) {
        uint32_t aw[4][4];
        int ar = mt * 16 + (lane & 7) + ((lane >> 3) & 1) * 8;
#pragma unroll
        for (int kc = 0; kc < 4; ++kc)
            ldsm4(aw[kc], sb + SW128(ar * 128 + kc * 32 + acolb));
#pragma unroll
        for (int nt = 0; nt < 2; ++nt)
#pragma unroll
            for (int kc = 0; kc < 4; ++kc)
                mma16816(co[mt][nt], aw[kc], &bx[nt][kc * 2]);
    }

    float gm = gamma[0];
#pragma unroll
    for (int mt = 0; mt < 4; ++mt) {
        int cA = c0 + mt * 16 + (lane >> 2);
        int cB = cA + 8;
        float bA = bv[cA], bB = bv[cB];
#pragma unroll
        for (int nt = 0; nt < 2; ++nt) {
            int pix = n0 + wpix0 + nt * 8 + (lane & 3) * 2;
            size_t iA = ((size_t)b * CCH + cA) * NPIX + pix;
            size_t iB = ((size_t)b * CCH + cB) * NPIX + pix;
            float2 xA = *(const float2*)&x[iA];
            float2 xB = *(const float2*)&x[iB];
            float2 oA, oB;
            oA.x = gm * (co[mt][nt][0] + bA) + xA.x;
            oA.y = gm * (co[mt][nt][1] + bA) + xA.y;
            oB.x = gm * (co[mt][nt][2] + bB) + xB.x;
            oB.y = gm * (co[mt][nt][3] + bB) + xB.y;
            *(float2*)&out[iA] = oA;
            *(float2*)&out[iB] = oB;
        }
    }
}

// ---------------------------------------------------------------------------
extern "C" void kernel_launch(void* const* d_in, const int* in_sizes, int n_in,
                              void* d_out, int out_size)
{
    const float* x     = (const float*)d_in[0];
    const float* Wf    = (const float*)d_in[1];
    const float* bf    = (const float*)d_in[2];
    const float* Wg    = (const float*)d_in[3];
    const float* bg    = (const float*)d_in[4];
    const float* Wh    = (const float*)d_in[5];
    const float* bh    = (const float*)d_in[6];
    const float* Wv    = (const float*)d_in[7];
    const float* bv    = (const float*)d_in[8];
    const float* uf    = (const float*)d_in[9];
    const float* ug    = (const float*)d_in[10];
    const float* uh    = (const float*)d_in[11];
    const float* uv    = (const float*)d_in[12];
    const float* gamma = (const float*)d_in[13];
    float* out = (float*)d_out;

    cudaFuncSetAttribute(attn_kernel, cudaFuncAttributeMaxDynamicSharedMemorySize, SM_ATTN_TOT);
    cudaFuncSetAttribute(proj_kernel, cudaFuncAttributeMaxDynamicSharedMemorySize, SM_PROJ_TOT);

    spectral_kernel<<<4, 512>>>(Wf, Wg, Wh, Wv, uf, ug, uh, uv);
    wconv_kernel<<<128, 256>>>(Wf, Wg, Wh, Wv);
    proj_kernel<<<dim3(NPIX / 128, BATCH), 256, SM_PROJ_TOT>>>(x, bf, bg, bh);
    attn_kernel<<<dim3(NPIX / 128, BATCH), 256, SM_ATTN_TOT>>>();
    outproj_kernel<<<dim3(NPIX / 128, CCH / 64, BATCH), 256>>>(x, bv, gamma, out);
}

// round 16
// speedup vs baseline: 2.0113x; 1.2989x over previous
#include <cuda_runtime.h>
#include <cuda_fp16.h>
#include <cstdint>
#include <math.h>

#define BATCH 4
#define CCH   512
#define HCH   64
#define NPIX  4096
#define LOG2E 1.4426950408889634f

// ---------------- device scratch ----------------
__device__ __align__(16) __half g_fT[BATCH * NPIX * HCH];   // f^T [n][64], pre-scaled log2e
__device__ __align__(16) __half g_gT[BATCH * NPIX * HCH];   // g^T [n][64]
__device__ __align__(16) __half g_h [BATCH * HCH * NPIX];   // h   [64][n]
__device__ __align__(16) __half g_oT[BATCH * NPIX * HCH];   // o^T [n][64]
__device__ __align__(16) __half g_Wp[3 * HCH * CCH];        // W' fp16 (invsig, log2e folded)
__device__ __align__(16) __half g_Wvp[CCH * HCH];           // Wv' fp16 (invsig folded)
__device__ float g_invsig[4];

// ---------------- helpers (baseline PTX only) ----------------
__device__ __forceinline__ uint32_t smem_u32(const void* p) {
    uint32_t a;
    asm("{ .reg .u64 t; cvta.to.shared.u64 t, %1; cvt.u32.u64 %0, t; }" : "=r"(a) : "l"(p));
    return a;
}
__device__ __forceinline__ float ex2(float x) {
    float y; asm("ex2.approx.ftz.f32 %0, %1;" : "=f"(y) : "f"(x)); return y;
}
#define SW128(o) ((o) ^ (((o) >> 3) & 0x70))

__device__ __forceinline__ void cp_async16(uint32_t dst, const void* src) {
    asm volatile("cp.async.cg.shared.global [%0], [%1], 16;" :: "r"(dst), "l"(src) : "memory");
}
#define CP_COMMIT() asm volatile("cp.async.commit_group;" ::: "memory")
#define CP_WAIT(n)  asm volatile("cp.async.wait_group %0;" :: "n"(n) : "memory")

__device__ __forceinline__ void ldsm4(uint32_t* r, uint32_t a) {
    asm volatile("ldmatrix.sync.aligned.m8n8.x4.shared.b16 {%0,%1,%2,%3}, [%4];"
                 : "=r"(r[0]), "=r"(r[1]), "=r"(r[2]), "=r"(r[3]) : "r"(a));
}
__device__ __forceinline__ void mma16816(float* c, const uint32_t* a, const uint32_t* b) {
    asm volatile("mma.sync.aligned.m16n8k16.row.col.f32.f16.f16.f32 "
                 "{%0,%1,%2,%3}, {%4,%5,%6,%7}, {%8,%9}, {%0,%1,%2,%3};"
                 : "+f"(c[0]), "+f"(c[1]), "+f"(c[2]), "+f"(c[3])
                 : "r"(a[0]), "r"(a[1]), "r"(a[2]), "r"(a[3]), "r"(b[0]), "r"(b[1]));
}
__device__ __forceinline__ uint32_t pack_h2(__half a, __half b) {
    __half2 t = __halves2half2(a, b);
    return *reinterpret_cast<uint32_t*>(&t);
}
// copy rows x 128B tile (half source) into SW128-swizzled smem, 256 threads
__device__ __forceinline__ void cp_tile(uint32_t sbase, const __half* src,
                                        size_t rstride, int tid, int rows) {
    int total = rows * 8;
    for (int c = tid; c < total; c += 256) {
        int row = c >> 3, j = c & 7;
        cp_async16(sbase + SW128(row * 128 + j * 16), src + row * rstride + j * 8);
    }
}

// ---------------------------------------------------------------------------
// Spectral norm: sigma = || W @ normalize(W^T u) ||.  All 512 threads active
// in BOTH dot-product phases (8 threads per skinny row/col + smem partials).
// ---------------------------------------------------------------------------
__global__ void spectral_kernel(const float* __restrict__ Wf, const float* __restrict__ Wg,
                                const float* __restrict__ Wh, const float* __restrict__ Wv,
                                const float* __restrict__ uf, const float* __restrict__ ug,
                                const float* __restrict__ uh, const float* __restrict__ uv)
{
    __shared__ float u_s[512], v_s[512], red[512], part[512];
    int w = blockIdx.x;
    const float* W; const float* u; int R, Cc;
    if (w == 0)      { W = Wf; u = uf; R = HCH; Cc = CCH; }
    else if (w == 1) { W = Wg; u = ug; R = HCH; Cc = CCH; }
    else if (w == 2) { W = Wh; u = uh; R = HCH; Cc = CCH; }
    else             { W = Wv; u = uv; R = CCH; Cc = HCH; }
    int t = threadIdx.x;
    if (t < R) u_s[t] = u[t];
    __syncthreads();

    // phase A: v = W^T u  (Cc elems)
    if (w < 3) {
        // Cc=512, R=64: one thread per column (already wide, coalesced)
        float v = 0.f;
        for (int r = 0; r < 64; ++r) v += W[r * 512 + t] * u_s[r];
        v_s[t] = v;
        red[t] = v * v;
    } else {
        // Cc=64, R=512: 8 threads per column, 64-row chunks (coalesced lanes)
        int col = t & 63, ch = t >> 6;
        float p = 0.f;
        int r0 = ch * 64;
        for (int r = 0; r < 64; ++r) p += W[(r0 + r) * 64 + col] * u_s[r0 + r];
        part[t] = p;
        __syncthreads();
        if (t < 64) {
            float v = 0.f;
#pragma unroll
            for (int k = 0; k < 8; ++k) v += part[k * 64 + t];
            v_s[t] = v;
            red[t] = v * v;
        } else red[t] = 0.f;
    }
    __syncthreads();
    for (int s = 256; s > 0; s >>= 1) { if (t < s) red[t] += red[t + s]; __syncthreads(); }
    float rn = rsqrtf(fmaxf(red[0], 1e-24f));
    if (t < Cc) v_s[t] *= rn;
    __syncthreads();

    // phase B: tv = W v (R elems), sigma = ||tv||
    if (w < 3) {
        // R=64, Cc=512: 8 threads per row, 64-col chunks
        int row = t >> 3, ch = t & 7;
        const float* rp = W + row * 512 + ch * 64;
        const float* vp = v_s + ch * 64;
        float p = 0.f;
        for (int c = 0; c < 64; ++c) p += rp[c] * vp[c];
        part[t] = p;
        __syncthreads();
        if (t < 64) {
            float tv = 0.f;
#pragma unroll
            for (int k = 0; k < 8; ++k) tv += part[t * 8 + k];
            red[t] = tv * tv;
        } else red[t] = 0.f;
    } else {
        // R=512, Cc=64: one thread per row
        const float* rp = W + t * 64;
        float tv = 0.f;
        for (int c = 0; c < 64; ++c) tv += rp[c] * v_s[c];
        red[t] = tv * tv;
    }
    __syncthreads();
    for (int s = 256; s > 0; s >>= 1) { if (t < s) red[t] += red[t + s]; __syncthreads(); }
    if (t == 0) g_invsig[w] = rsqrtf(fmaxf(red[0], 1e-24f));
}

// ---------------------------------------------------------------------------
// Weight conversion: fold invsig (and log2e for Wf) into fp16 weights.
// ---------------------------------------------------------------------------
__global__ void wconv_kernel(const float* __restrict__ Wf, const float* __restrict__ Wg,
                             const float* __restrict__ Wh, const float* __restrict__ Wv)
{
    int idx = blockIdx.x * 256 + threadIdx.x;
    int stride = gridDim.x * 256;
    for (int i = idx; i < 3 * HCH * CCH + CCH * HCH; i += stride) {
        if (i < 3 * HCH * CCH) {
            int w = i / (HCH * CCH), r = i % (HCH * CCH);
            const float* W = (w == 0) ? Wf : ((w == 1) ? Wg : Wh);
            float scl = g_invsig[w] * (w == 0 ? LOG2E : 1.0f);
            g_Wp[i] = __float2half_rn(W[r] * scl);
        } else {
            int r = i - 3 * HCH * CCH;
            g_Wvp[r] = __float2half_rn(Wv[r] * g_invsig[3]);
        }
    }
}

// ---------------------------------------------------------------------------
// Fused MMA projections: one CTA = [128 pix] x one batch; computes f,g,h.
// fT/gT written [pix][64]; h written [64][pix].  grid (32, 4), 256 threads.
// ---------------------------------------------------------------------------
#define PX_XRAW 0
#define PX_XT   65536
#define PX_W    81920
#define PX_BIAS 155648
#define SM_PROJ_TOT 156416

__device__ __forceinline__ void cp_xraw(uint32_t sb, int buf, const float* xb,
                                        int c, int n0, int tid) {
    for (int idx = tid; idx < 64 * 32; idx += 256) {
        int row = idx >> 5, jj = idx & 31;
        cp_async16(sb + PX_XRAW + buf * 32768 + row * 512 + ((jj ^ (row & 7)) << 4),
                   xb + (size_t)(c * 64 + row) * NPIX + n0 + jj * 4);
    }
}
__device__ __forceinline__ void cp_Wchunk(uint32_t sb, int buf, int c, int tid) {
#pragma unroll
    for (int w = 0; w < 3; ++w)
        cp_tile(sb + PX_W + buf * 24576 + w * 8192, g_Wp + w * 32768 + c * 64, 512, tid, 64);
}

__global__ void __launch_bounds__(256, 1) proj_kernel(
    const float* __restrict__ x,
    const float* __restrict__ bf, const float* __restrict__ bg, const float* __restrict__ bh)
{
    extern __shared__ __align__(128) char smem[];
    int tid = threadIdx.x;
    int lane = tid & 31, wid = tid >> 5;
    int wpix0 = wid * 16;
    int nb = blockIdx.x, b = blockIdx.y;
    int n0 = nb * 128;
    uint32_t sb = smem_u32(smem);
    const float* xb = x + (size_t)b * CCH * NPIX;

    cp_xraw(sb, 0, xb, 0, n0, tid); cp_Wchunk(sb, 0, 0, tid); CP_COMMIT();
    cp_xraw(sb, 1, xb, 1, n0, tid); cp_Wchunk(sb, 1, 1, tid); CP_COMMIT();

    float* bias_s = (float*)(smem + PX_BIAS);
    if (tid < 192) {
        int w = tid >> 6, d = tid & 63;
        bias_s[tid] = (w == 0) ? bf[d] * LOG2E : ((w == 1) ? bg[d] : bh[d]);
    }

    float cf[8][4], cg[8][4], chh[4][2][4];
#pragma unroll
    for (int i = 0; i < 8; ++i)
#pragma unroll
        for (int j = 0; j < 4; ++j) { cf[i][j] = 0.f; cg[i][j] = 0.f; }
#pragma unroll
    for (int i = 0; i < 4; ++i)
#pragma unroll
        for (int n = 0; n < 2; ++n)
#pragma unroll
            for (int j = 0; j < 4; ++j) chh[i][n][j] = 0.f;

    int brow = lane & 7;
    int bj = lane >> 3;
    int bcol = (bj & 1) * 16 + (bj >> 1) * 32;
    int acolb = ((lane >> 4) & 1) * 16;

    for (int c = 0; c < 8; ++c) {
        CP_WAIT(1);
        __syncthreads();
        // convert xraw[c&1] -> xT [pix][64] fp16 swizzled
        {
            int ch = tid & 63, q4 = tid >> 6;
            const char* xr = smem + PX_XRAW + (c & 1) * 32768 + ch * 512;
#pragma unroll
            for (int i = 0; i < 8; ++i) {
                int j = q4 * 8 + i;
                float4 v = *(const float4*)(xr + ((j ^ (ch & 7)) << 4));
                int p = j * 4;
                *(__half*)(smem + PX_XT + SW128((p + 0) * 128 + ch * 2)) = __float2half_rn(v.x);
                *(__half*)(smem + PX_XT + SW128((p + 1) * 128 + ch * 2)) = __float2half_rn(v.y);
                *(__half*)(smem + PX_XT + SW128((p + 2) * 128 + ch * 2)) = __float2half_rn(v.z);
                *(__half*)(smem + PX_XT + SW128((p + 3) * 128 + ch * 2)) = __float2half_rn(v.w);
            }
        }
        __syncthreads();
        if (c < 6) {
            cp_xraw(sb, c & 1, xb, c + 2, n0, tid);
            cp_Wchunk(sb, (c + 2) % 3, c + 2, tid);
            CP_COMMIT();
        }
        // MMA
        uint32_t xtb = sb + PX_XT;
        uint32_t wtb = sb + PX_W + (c % 3) * 24576;
        uint32_t ax[4][4];
        int arow = wpix0 + (lane & 7) + ((lane >> 3) & 1) * 8;
#pragma unroll
        for (int kc = 0; kc < 4; ++kc)
            ldsm4(ax[kc], xtb + SW128(arow * 128 + kc * 32 + acolb));
        // f
#pragma unroll
        for (int nt = 0; nt < 8; ++nt) {
            uint32_t bw[8];
            uint32_t o0 = SW128((nt * 8 + brow) * 128 + bcol);
            uint32_t o1 = SW128((nt * 8 + brow) * 128 + 64 + bcol);
            ldsm4(bw, wtb + o0); ldsm4(bw + 4, wtb + o1);
#pragma unroll
            for (int kc = 0; kc < 4; ++kc) mma16816(cf[nt], ax[kc], &bw[kc * 2]);
        }
        // g
#pragma unroll
        for (int nt = 0; nt < 8; ++nt) {
            uint32_t bw[8];
            uint32_t o0 = SW128((nt * 8 + brow) * 128 + bcol);
            uint32_t o1 = SW128((nt * 8 + brow) * 128 + 64 + bcol);
            ldsm4(bw, wtb + 8192 + o0); ldsm4(bw + 4, wtb + 8192 + o1);
#pragma unroll
            for (int kc = 0; kc < 4; ++kc) mma16816(cg[nt], ax[kc], &bw[kc * 2]);
        }
        // h
        uint32_t bx[2][8];
#pragma unroll
        for (int nt = 0; nt < 2; ++nt) {
            uint32_t o0 = SW128((wpix0 + nt * 8 + brow) * 128 + bcol);
            uint32_t o1 = SW128((wpix0 + nt * 8 + brow) * 128 + 64 + bcol);
            ldsm4(bx[nt], xtb + o0); ldsm4(bx[nt] + 4, xtb + o1);
        }
#pragma unroll
        for (int mt = 0; mt < 4; ++mt) {
            uint32_t aw[4][4];
            int ar = mt * 16 + (lane & 7) + ((lane >> 3) & 1) * 8;
#pragma unroll
            for (int kc = 0; kc < 4; ++kc)
                ldsm4(aw[kc], wtb + 16384 + SW128(ar * 128 + kc * 32 + acolb));
#pragma unroll
            for (int nt = 0; nt < 2; ++nt)
#pragma unroll
                for (int kc = 0; kc < 4; ++kc)
                    mma16816(chh[mt][nt], aw[kc], &bx[nt][kc * 2]);
        }
    }

    // epilogue
    int q = wpix0 + (lane >> 2);
    size_t fbase = (size_t)b * NPIX * HCH + (size_t)(n0 + q) * HCH;
#pragma unroll
    for (int nt = 0; nt < 8; ++nt) {
        int d = nt * 8 + (lane & 3) * 2;
        float b0 = bias_s[d], b1 = bias_s[d + 1];
        *(uint32_t*)&g_fT[fbase + d] =
            pack_h2(__float2half_rn(cf[nt][0] + b0), __float2half_rn(cf[nt][1] + b1));
        *(uint32_t*)&g_fT[fbase + 8 * HCH + d] =
            pack_h2(__float2half_rn(cf[nt][2] + b0), __float2half_rn(cf[nt][3] + b1));
        float c0g = bias_s[64 + d], c1g = bias_s[64 + d + 1];
        *(uint32_t*)&g_gT[fbase + d] =
            pack_h2(__float2half_rn(cg[nt][0] + c0g), __float2half_rn(cg[nt][1] + c1g));
        *(uint32_t*)&g_gT[fbase + 8 * HCH + d] =
            pack_h2(__float2half_rn(cg[nt][2] + c0g), __float2half_rn(cg[nt][3] + c1g));
    }
    __half* Hp = g_h + (size_t)b * HCH * NPIX;
#pragma unroll
    for (int mt = 0; mt < 4; ++mt) {
        int d0 = mt * 16 + (lane >> 2), d1 = d0 + 8;
        float bb0 = bias_s[128 + d0], bb1 = bias_s[128 + d1];
#pragma unroll
        for (int nt = 0; nt < 2; ++nt) {
            int pix = n0 + wpix0 + nt * 8 + (lane & 3) * 2;
            *(uint32_t*)&Hp[(size_t)d0 * NPIX + pix] =
                pack_h2(__float2half_rn(chh[mt][nt][0] + bb0), __float2half_rn(chh[mt][nt][1] + bb0));
            *(uint32_t*)&Hp[(size_t)d1 * NPIX + pix] =
                pack_h2(__float2half_rn(chh[mt][nt][2] + bb1), __float2half_rn(chh[mt][nt][3] + bb1));
        }
    }
}

// ---------------------------------------------------------------------------
// mma.sync (fp16) flash attention.  grid (32, B), 256 threads (8 warps x 16 q).
// ---------------------------------------------------------------------------
#define SM_FH 0
#define SM_BUF 16384
#define SM_ATTN_TOT 49152

__global__ void __launch_bounds__(256, 1) attn_kernel()
{
    extern __shared__ __align__(128) char smem[];
    int tid = threadIdx.x;
    int lane = tid & 31, wid = tid >> 5;
    int m0 = wid * 16;
    int b = blockIdx.y, n0 = blockIdx.x * 128;
    uint32_t sb = smem_u32(smem);

    size_t bo = (size_t)b * NPIX * HCH;
    const __half* fT = g_fT + bo + (size_t)n0 * HCH;
    const __half* gT = g_gT + bo;
    const __half* hp = g_h + (size_t)b * HCH * NPIX;

    cp_tile(sb + SM_FH, fT, 64, tid, 128);
    cp_tile(sb + SM_BUF,        gT, 64, tid, 64);
    cp_tile(sb + SM_BUF + 8192, hp, NPIX, tid, 64);
    CP_COMMIT();
    cp_tile(sb + SM_BUF + 16384, gT + 64 * 64, 64, tid, 64);
    cp_tile(sb + SM_BUF + 24576, hp + 64, NPIX, tid, 64);
    CP_COMMIT();

    CP_WAIT(1);
    __syncthreads();

    uint32_t fa[4][4];
    {
        int arow = m0 + (lane & 7) + ((lane >> 3) & 1) * 8;
        int acol = ((lane >> 4) & 1) * 16;
#pragma unroll
        for (int kc = 0; kc < 4; ++kc)
            ldsm4(fa[kc], sb + SM_FH + SW128(arow * 128 + kc * 32 + acol));
    }

    float oaccv[32];
#pragma unroll
    for (int i = 0; i < 32; ++i) oaccv[i] = 0.f;
    float m0r = -1e30f, m1r = -1e30f, l0 = 0.f, l1 = 0.f;

    int brow = lane & 7;
    int bj = lane >> 3;
    int bcol = (bj & 1) * 16 + (bj >> 1) * 32;

    for (int kt = 0; kt < 64; ++kt) {
        if (kt > 0) { CP_WAIT(1); __syncthreads(); }
        uint32_t gB = sb + SM_BUF + (kt & 1) * 16384;
        uint32_t hB = gB + 8192;

        float s[32];
#pragma unroll
        for (int i = 0; i < 32; ++i) s[i] = 0.f;
#pragma unroll
        for (int nt = 0; nt < 8; ++nt) {
            uint32_t bfr[8];
            uint32_t o0 = SW128((nt * 8 + brow) * 128 + 0 + bcol);
            uint32_t o1 = SW128((nt * 8 + brow) * 128 + 64 + bcol);
            ldsm4(bfr,     gB + o0);
            ldsm4(bfr + 4, gB + o1);
            float* s4 = &s[nt * 4];
#pragma unroll
            for (int kc = 0; kc < 4; ++kc) mma16816(s4, fa[kc], &bfr[kc * 2]);
        }

        float mx0 = -1e30f, mx1 = -1e30f;
#pragma unroll
        for (int nt = 0; nt < 8; ++nt) {
            mx0 = fmaxf(mx0, fmaxf(s[nt * 4 + 0], s[nt * 4 + 1]));
            mx1 = fmaxf(mx1, fmaxf(s[nt * 4 + 2], s[nt * 4 + 3]));
        }
        mx0 = fmaxf(mx0, __shfl_xor_sync(0xffffffffu, mx0, 1));
        mx0 = fmaxf(mx0, __shfl_xor_sync(0xffffffffu, mx0, 2));
        mx1 = fmaxf(mx1, __shfl_xor_sync(0xffffffffu, mx1, 1));
        mx1 = fmaxf(mx1, __shfl_xor_sync(0xffffffffu, mx1, 2));
        float mn0 = fmaxf(m0r, mx0), mn1 = fmaxf(m1r, mx1);
        float c0 = ex2(m0r - mn0), c1 = ex2(m1r - mn1);
        m0r = mn0; m1r = mn1;
        float ls0 = 0.f, ls1 = 0.f;
#pragma unroll
        for (int nt = 0; nt < 8; ++nt) {
            float p0 = ex2(s[nt * 4 + 0] - mn0);
            float p1 = ex2(s[nt * 4 + 1] - mn0);
            float p2 = ex2(s[nt * 4 + 2] - mn1);
            float p3 = ex2(s[nt * 4 + 3] - mn1);
            s[nt * 4 + 0] = p0; s[nt * 4 + 1] = p1;
            s[nt * 4 + 2] = p2; s[nt * 4 + 3] = p3;
            ls0 += p0 + p1; ls1 += p2 + p3;
        }
        l0 = l0 * c0 + ls0;
        l1 = l1 * c1 + ls1;
#pragma unroll
        for (int nt = 0; nt < 8; ++nt) {
            oaccv[nt * 4 + 0] *= c0; oaccv[nt * 4 + 1] *= c0;
            oaccv[nt * 4 + 2] *= c1; oaccv[nt * 4 + 3] *= c1;
        }

        uint32_t pa[4][4];
#pragma unroll
        for (int j = 0; j < 4; ++j) {
            float* sa = &s[(2 * j) * 4];
            float* sc = &s[(2 * j + 1) * 4];
            pa[j][0] = pack_h2(__float2half_rn(sa[0]), __float2half_rn(sa[1]));
            pa[j][1] = pack_h2(__float2half_rn(sa[2]), __float2half_rn(sa[3]));
            pa[j][2] = pack_h2(__float2half_rn(sc[0]), __float2half_rn(sc[1]));
            pa[j][3] = pack_h2(__float2half_rn(sc[2]), __float2half_rn(sc[3]));
        }

#pragma unroll
        for (int nd = 0; nd < 8; ++nd) {
            uint32_t bfr[8];
            uint32_t o0 = SW128((nd * 8 + brow) * 128 + 0 + bcol);
            uint32_t o1 = SW128((nd * 8 + brow) * 128 + 64 + bcol);
            ldsm4(bfr,     hB + o0);
            ldsm4(bfr + 4, hB + o1);
            float* o4 = &oaccv[nd * 4];
#pragma unroll
            for (int j = 0; j < 4; ++j) mma16816(o4, pa[j], &bfr[j * 2]);
        }

        __syncthreads();
        if (kt < 62) {
            uint32_t bb = sb + SM_BUF + (kt & 1) * 16384;
            cp_tile(bb,        gT + (size_t)(kt + 2) * 64 * 64, 64, tid, 64);
            cp_tile(bb + 8192, hp + (kt + 2) * 64, NPIX, tid, 64);
            CP_COMMIT();
        }
    }

    // epilogue: write o^T fp16 [pix][64] directly from fragments
    l0 += __shfl_xor_sync(0xffffffffu, l0, 1);
    l0 += __shfl_xor_sync(0xffffffffu, l0, 2);
    l1 += __shfl_xor_sync(0xffffffffu, l1, 1);
    l1 += __shfl_xor_sync(0xffffffffu, l1, 2);
    float inv0 = 1.f / l0, inv1 = 1.f / l1;

    int q0 = m0 + (lane >> 2), q1 = q0 + 8;
    size_t r0 = (size_t)b * NPIX * HCH + (size_t)(n0 + q0) * HCH;
    size_t r1 = (size_t)b * NPIX * HCH + (size_t)(n0 + q1) * HCH;
#pragma unroll
    for (int nt = 0; nt < 8; ++nt) {
        int d = nt * 8 + (lane & 3) * 2;
        *(uint32_t*)&g_oT[r0 + d] = pack_h2(__float2half_rn(oaccv[nt * 4 + 0] * inv0),
                                            __float2half_rn(oaccv[nt * 4 + 1] * inv0));
        *(uint32_t*)&g_oT[r1 + d] = pack_h2(__float2half_rn(oaccv[nt * 4 + 2] * inv1),
                                            __float2half_rn(oaccv[nt * 4 + 3] * inv1));
    }
}

// ---------------------------------------------------------------------------
// MMA outproj: out = gamma*(Wv' @ o + bv) + x.  grid (32, 8, 4), 256 threads.
// ---------------------------------------------------------------------------
__global__ void __launch_bounds__(256) outproj_kernel(
    const float* __restrict__ x, const float* __restrict__ bv,
    const float* __restrict__ gamma, float* __restrict__ out)
{
    __shared__ __align__(1024) char osm[24576];   // Wv tile 8KB @0, oT tile 16KB @8192
    int tid = threadIdx.x;
    int lane = tid & 31, wid = tid >> 5;
    int wpix0 = wid * 16;
    int nb = blockIdx.x, ct = blockIdx.y, b = blockIdx.z;
    int n0 = nb * 128, c0 = ct * 64;
    uint32_t sb = smem_u32(osm);

    cp_tile(sb, g_Wvp + c0 * 64, 64, tid, 64);
    cp_tile(sb + 8192, g_oT + ((size_t)b * NPIX + n0) * 64, 64, tid, 128);
    CP_COMMIT();
    CP_WAIT(0);
    __syncthreads();

    int brow = lane & 7;
    int bj = lane >> 3;
    int bcol = (bj & 1) * 16 + (bj >> 1) * 32;
    int acolb = ((lane >> 4) & 1) * 16;

    float co[4][2][4];
#pragma unroll
    for (int i = 0; i < 4; ++i)
#pragma unroll
        for (int n = 0; n < 2; ++n)
#pragma unroll
            for (int j = 0; j < 4; ++j) co[i][n][j] = 0.f;

    uint32_t bx[2][8];
#pragma unroll
    for (int nt = 0; nt < 2; ++nt) {
        uint32_t o0 = SW128((wpix0 + nt * 8 + brow) * 128 + bcol);
        uint32_t o1 = SW128((wpix0 + nt * 8 + brow) * 128 + 64 + bcol);
        ldsm4(bx[nt], sb + 8192 + o0); ldsm4(bx[nt] + 4, sb + 8192 + o1);
    }
#pragma unroll
    for (int mt = 0; mt < 4; ++mt) {
        uint32_t aw[4][4];
        int ar = mt * 16 + (lane & 7) + ((lane >> 3) & 1) * 8;
#pragma unroll
        for (int kc = 0; kc < 4; ++kc)
            ldsm4(aw[kc], sb + SW128(ar * 128 + kc * 32 + acolb));
#pragma unroll
        for (int nt = 0; nt < 2; ++nt)
#pragma unroll
            for (int kc = 0; kc < 4; ++kc)
                mma16816(co[mt][nt], aw[kc], &bx[nt][kc * 2]);
    }

    float gm = gamma[0];
#pragma unroll
    for (int mt = 0; mt < 4; ++mt) {
        int cA = c0 + mt * 16 + (lane >> 2);
        int cB = cA + 8;
        float bA = bv[cA], bB = bv[cB];
#pragma unroll
        for (int nt = 0; nt < 2; ++nt) {
            int pix = n0 + wpix0 + nt * 8 + (lane & 3) * 2;
            size_t iA = ((size_t)b * CCH + cA) * NPIX + pix;
            size_t iB = ((size_t)b * CCH + cB) * NPIX + pix;
            float2 xA = *(const float2*)&x[iA];
            float2 xB = *(const float2*)&x[iB];
            float2 oA, oB;
            oA.x = gm * (co[mt][nt][0] + bA) + xA.x;
            oA.y = gm * (co[mt][nt][1] + bA) + xA.y;
            oB.x = gm * (co[mt][nt][2] + bB) + xB.x;
            oB.y = gm * (co[mt][nt][3] + bB) + xB.y;
            *(float2*)&out[iA] = oA;
            *(float2*)&out[iB] = oB;
        }
    }
}

// ---------------------------------------------------------------------------
extern "C" void kernel_launch(void* const* d_in, const int* in_sizes, int n_in,
                              void* d_out, int out_size)
{
    const float* x     = (const float*)d_in[0];
    const float* Wf    = (const float*)d_in[1];
    const float* bf    = (const float*)d_in[2];
    const float* Wg    = (const float*)d_in[3];
    const float* bg    = (const float*)d_in[4];
    const float* Wh    = (const float*)d_in[5];
    const float* bh    = (const float*)d_in[6];
    const float* Wv    = (const float*)d_in[7];
    const float* bv    = (const float*)d_in[8];
    const float* uf    = (const float*)d_in[9];
    const float* ug    = (const float*)d_in[10];
    const float* uh    = (const float*)d_in[11];
    const float* uv    = (const float*)d_in[12];
    const float* gamma = (const float*)d_in[13];
    float* out = (float*)d_out;

    cudaFuncSetAttribute(attn_kernel, cudaFuncAttributeMaxDynamicSharedMemorySize, SM_ATTN_TOT);
    cudaFuncSetAttribute(proj_kernel, cudaFuncAttributeMaxDynamicSharedMemorySize, SM_PROJ_TOT);

    spectral_kernel<<<4, 512>>>(Wf, Wg, Wh, Wv, uf, ug, uh, uv);
    wconv_kernel<<<128, 256>>>(Wf, Wg, Wh, Wv);
    proj_kernel<<<dim3(NPIX / 128, BATCH), 256, SM_PROJ_TOT>>>(x, bf, bg, bh);
    attn_kernel<<<dim3(NPIX / 128, BATCH), 256, SM_ATTN_TOT>>>();
    outproj_kernel<<<dim3(NPIX / 128, CCH / 64, BATCH), 256>>>(x, bv, gamma, out);
}

// round 17
// speedup vs baseline: 2.0346x; 1.0116x over previous
#include <cuda_runtime.h>
#include <cuda_fp16.h>
#include <cstdint>
#include <math.h>

#define BATCH 4
#define CCH   512
#define HCH   64
#define NPIX  4096
#define LOG2E 1.4426950408889634f

// ---------------- device scratch ----------------
__device__ __align__(16) __half g_fT[BATCH * NPIX * HCH];   // f^T [n][64], pre-scaled log2e
__device__ __align__(16) __half g_gT[BATCH * NPIX * HCH];   // g^T [n][64]
__device__ __align__(16) __half g_h [BATCH * HCH * NPIX];   // h   [64][n]
__device__ __align__(16) __half g_oT[BATCH * NPIX * HCH];   // o^T [n][64]
__device__ __align__(16) __half g_Wp[3 * HCH * CCH];        // W' fp16 (invsig, log2e folded)
__device__ __align__(16) __half g_Wvp[CCH * HCH];           // Wv' fp16 (invsig folded)
__device__ float g_invsig[4];

// ---------------- helpers (baseline PTX only) ----------------
__device__ __forceinline__ uint32_t smem_u32(const void* p) {
    uint32_t a;
    asm("{ .reg .u64 t; cvta.to.shared.u64 t, %1; cvt.u32.u64 %0, t; }" : "=r"(a) : "l"(p));
    return a;
}
__device__ __forceinline__ float ex2(float x) {
    float y; asm("ex2.approx.ftz.f32 %0, %1;" : "=f"(y) : "f"(x)); return y;
}
#define SW128(o) ((o) ^ (((o) >> 3) & 0x70))

__device__ __forceinline__ void cp_async16(uint32_t dst, const void* src) {
    asm volatile("cp.async.cg.shared.global [%0], [%1], 16;" :: "r"(dst), "l"(src) : "memory");
}
#define CP_COMMIT() asm volatile("cp.async.commit_group;" ::: "memory")
#define CP_WAIT(n)  asm volatile("cp.async.wait_group %0;" :: "n"(n) : "memory")

__device__ __forceinline__ void ldsm4(uint32_t* r, uint32_t a) {
    asm volatile("ldmatrix.sync.aligned.m8n8.x4.shared.b16 {%0,%1,%2,%3}, [%4];"
                 : "=r"(r[0]), "=r"(r[1]), "=r"(r[2]), "=r"(r[3]) : "r"(a));
}
__device__ __forceinline__ void mma16816(float* c, const uint32_t* a, const uint32_t* b) {
    asm volatile("mma.sync.aligned.m16n8k16.row.col.f32.f16.f16.f32 "
                 "{%0,%1,%2,%3}, {%4,%5,%6,%7}, {%8,%9}, {%0,%1,%2,%3};"
                 : "+f"(c[0]), "+f"(c[1]), "+f"(c[2]), "+f"(c[3])
                 : "r"(a[0]), "r"(a[1]), "r"(a[2]), "r"(a[3]), "r"(b[0]), "r"(b[1]));
}
__device__ __forceinline__ uint32_t pack_h2(__half a, __half b) {
    __half2 t = __halves2half2(a, b);
    return *reinterpret_cast<uint32_t*>(&t);
}
// copy rows x 128B tile (half source) into SW128-swizzled smem, 256 threads
__device__ __forceinline__ void cp_tile(uint32_t sbase, const __half* src,
                                        size_t rstride, int tid, int rows) {
    int total = rows * 8;
    for (int c = tid; c < total; c += 256) {
        int row = c >> 3, j = c & 7;
        cp_async16(sbase + SW128(row * 128 + j * 16), src + row * rstride + j * 8);
    }
}

// ---------------------------------------------------------------------------
// Spectral norm: sigma = || W @ normalize(W^T u) ||.  All 512 threads active
// in BOTH dot-product phases (8 threads per skinny row/col + smem partials).
// ---------------------------------------------------------------------------
__global__ void spectral_kernel(const float* __restrict__ Wf, const float* __restrict__ Wg,
                                const float* __restrict__ Wh, const float* __restrict__ Wv,
                                const float* __restrict__ uf, const float* __restrict__ ug,
                                const float* __restrict__ uh, const float* __restrict__ uv)
{
    __shared__ float u_s[512], v_s[512], red[512], part[512];
    int w = blockIdx.x;
    const float* W; const float* u; int R, Cc;
    if (w == 0)      { W = Wf; u = uf; R = HCH; Cc = CCH; }
    else if (w == 1) { W = Wg; u = ug; R = HCH; Cc = CCH; }
    else if (w == 2) { W = Wh; u = uh; R = HCH; Cc = CCH; }
    else             { W = Wv; u = uv; R = CCH; Cc = HCH; }
    int t = threadIdx.x;
    if (t < R) u_s[t] = u[t];
    __syncthreads();

    // phase A: v = W^T u  (Cc elems)
    if (w < 3) {
        float v = 0.f;
        for (int r = 0; r < 64; ++r) v += W[r * 512 + t] * u_s[r];
        v_s[t] = v;
        red[t] = v * v;
    } else {
        int col = t & 63, ch = t >> 6;
        float p = 0.f;
        int r0 = ch * 64;
        for (int r = 0; r < 64; ++r) p += W[(r0 + r) * 64 + col] * u_s[r0 + r];
        part[t] = p;
        __syncthreads();
        if (t < 64) {
            float v = 0.f;
#pragma unroll
            for (int k = 0; k < 8; ++k) v += part[k * 64 + t];
            v_s[t] = v;
            red[t] = v * v;
        } else red[t] = 0.f;
    }
    __syncthreads();
    for (int s = 256; s > 0; s >>= 1) { if (t < s) red[t] += red[t + s]; __syncthreads(); }
    float rn = rsqrtf(fmaxf(red[0], 1e-24f));
    if (t < Cc) v_s[t] *= rn;
    __syncthreads();

    // phase B: tv = W v (R elems), sigma = ||tv||
    if (w < 3) {
        int row = t >> 3, ch = t & 7;
        const float* rp = W + row * 512 + ch * 64;
        const float* vp = v_s + ch * 64;
        float p = 0.f;
        for (int c = 0; c < 64; ++c) p += rp[c] * vp[c];
        part[t] = p;
        __syncthreads();
        if (t < 64) {
            float tv = 0.f;
#pragma unroll
            for (int k = 0; k < 8; ++k) tv += part[t * 8 + k];
            red[t] = tv * tv;
        } else red[t] = 0.f;
    } else {
        const float* rp = W + t * 64;
        float tv = 0.f;
        for (int c = 0; c < 64; ++c) tv += rp[c] * v_s[c];
        red[t] = tv * tv;
    }
    __syncthreads();
    for (int s = 256; s > 0; s >>= 1) { if (t < s) red[t] += red[t + s]; __syncthreads(); }
    if (t == 0) g_invsig[w] = rsqrtf(fmaxf(red[0], 1e-24f));
}

// ---------------------------------------------------------------------------
// Weight conversion: fold invsig (and log2e for Wf) into fp16 weights.
// ---------------------------------------------------------------------------
__global__ void wconv_kernel(const float* __restrict__ Wf, const float* __restrict__ Wg,
                             const float* __restrict__ Wh, const float* __restrict__ Wv)
{
    int idx = blockIdx.x * 256 + threadIdx.x;
    int stride = gridDim.x * 256;
    for (int i = idx; i < 3 * HCH * CCH + CCH * HCH; i += stride) {
        if (i < 3 * HCH * CCH) {
            int w = i / (HCH * CCH), r = i % (HCH * CCH);
            const float* W = (w == 0) ? Wf : ((w == 1) ? Wg : Wh);
            float scl = g_invsig[w] * (w == 0 ? LOG2E : 1.0f);
            g_Wp[i] = __float2half_rn(W[r] * scl);
        } else {
            int r = i - 3 * HCH * CCH;
            g_Wvp[r] = __float2half_rn(Wv[r] * g_invsig[3]);
        }
    }
}

// ---------------------------------------------------------------------------
// Fused MMA projections: one CTA = [128 pix] x one batch; computes f,g,h.
// fT/gT written [pix][64]; h written [64][pix].  grid (32, 4), 256 threads.
// ---------------------------------------------------------------------------
#define PX_XRAW 0
#define PX_XT   65536
#define PX_W    81920
#define PX_BIAS 155648
#define SM_PROJ_TOT 156416

__device__ __forceinline__ void cp_xraw(uint32_t sb, int buf, const float* xb,
                                        int c, int n0, int tid) {
    for (int idx = tid; idx < 64 * 32; idx += 256) {
        int row = idx >> 5, jj = idx & 31;
        cp_async16(sb + PX_XRAW + buf * 32768 + row * 512 + ((jj ^ (row & 7)) << 4),
                   xb + (size_t)(c * 64 + row) * NPIX + n0 + jj * 4);
    }
}
__device__ __forceinline__ void cp_Wchunk(uint32_t sb, int buf, int c, int tid) {
#pragma unroll
    for (int w = 0; w < 3; ++w)
        cp_tile(sb + PX_W + buf * 24576 + w * 8192, g_Wp + w * 32768 + c * 64, 512, tid, 64);
}

__global__ void __launch_bounds__(256, 1) proj_kernel(
    const float* __restrict__ x,
    const float* __restrict__ bf, const float* __restrict__ bg, const float* __restrict__ bh)
{
    extern __shared__ __align__(128) char smem[];
    int tid = threadIdx.x;
    int lane = tid & 31, wid = tid >> 5;
    int wpix0 = wid * 16;
    int nb = blockIdx.x, b = blockIdx.y;
    int n0 = nb * 128;
    uint32_t sb = smem_u32(smem);
    const float* xb = x + (size_t)b * CCH * NPIX;

    cp_xraw(sb, 0, xb, 0, n0, tid); cp_Wchunk(sb, 0, 0, tid); CP_COMMIT();
    cp_xraw(sb, 1, xb, 1, n0, tid); cp_Wchunk(sb, 1, 1, tid); CP_COMMIT();

    float* bias_s = (float*)(smem + PX_BIAS);
    if (tid < 192) {
        int w = tid >> 6, d = tid & 63;
        bias_s[tid] = (w == 0) ? bf[d] * LOG2E : ((w == 1) ? bg[d] : bh[d]);
    }

    float cf[8][4], cg[8][4], chh[4][2][4];
#pragma unroll
    for (int i = 0; i < 8; ++i)
#pragma unroll
        for (int j = 0; j < 4; ++j) { cf[i][j] = 0.f; cg[i][j] = 0.f; }
#pragma unroll
    for (int i = 0; i < 4; ++i)
#pragma unroll
        for (int n = 0; n < 2; ++n)
#pragma unroll
            for (int j = 0; j < 4; ++j) chh[i][n][j] = 0.f;

    int brow = lane & 7;
    int bj = lane >> 3;
    int bcol = (bj & 1) * 16 + (bj >> 1) * 32;
    int acolb = ((lane >> 4) & 1) * 16;

    for (int c = 0; c < 8; ++c) {
        CP_WAIT(1);
        __syncthreads();
        // convert xraw[c&1] -> xT [pix][64] fp16 swizzled
        {
            int ch = tid & 63, q4 = tid >> 6;
            const char* xr = smem + PX_XRAW + (c & 1) * 32768 + ch * 512;
#pragma unroll
            for (int i = 0; i < 8; ++i) {
                int j = q4 * 8 + i;
                float4 v = *(const float4*)(xr + ((j ^ (ch & 7)) << 4));
                int p = j * 4;
                *(__half*)(smem + PX_XT + SW128((p + 0) * 128 + ch * 2)) = __float2half_rn(v.x);
                *(__half*)(smem + PX_XT + SW128((p + 1) * 128 + ch * 2)) = __float2half_rn(v.y);
                *(__half*)(smem + PX_XT + SW128((p + 2) * 128 + ch * 2)) = __float2half_rn(v.z);
                *(__half*)(smem + PX_XT + SW128((p + 3) * 128 + ch * 2)) = __float2half_rn(v.w);
            }
        }
        __syncthreads();
        if (c < 6) {
            cp_xraw(sb, c & 1, xb, c + 2, n0, tid);
            cp_Wchunk(sb, (c + 2) % 3, c + 2, tid);
            CP_COMMIT();
        }
        // MMA
        uint32_t xtb = sb + PX_XT;
        uint32_t wtb = sb + PX_W + (c % 3) * 24576;
        uint32_t ax[4][4];
        int arow = wpix0 + (lane & 7) + ((lane >> 3) & 1) * 8;
#pragma unroll
        for (int kc = 0; kc < 4; ++kc)
            ldsm4(ax[kc], xtb + SW128(arow * 128 + kc * 32 + acolb));
        // f
#pragma unroll
        for (int nt = 0; nt < 8; ++nt) {
            uint32_t bw[8];
            uint32_t o0 = SW128((nt * 8 + brow) * 128 + bcol);
            uint32_t o1 = SW128((nt * 8 + brow) * 128 + 64 + bcol);
            ldsm4(bw, wtb + o0); ldsm4(bw + 4, wtb + o1);
#pragma unroll
            for (int kc = 0; kc < 4; ++kc) mma16816(cf[nt], ax[kc], &bw[kc * 2]);
        }
        // g
#pragma unroll
        for (int nt = 0; nt < 8; ++nt) {
            uint32_t bw[8];
            uint32_t o0 = SW128((nt * 8 + brow) * 128 + bcol);
            uint32_t o1 = SW128((nt * 8 + brow) * 128 + 64 + bcol);
            ldsm4(bw, wtb + 8192 + o0); ldsm4(bw + 4, wtb + 8192 + o1);
#pragma unroll
            for (int kc = 0; kc < 4; ++kc) mma16816(cg[nt], ax[kc], &bw[kc * 2]);
        }
        // h
        uint32_t bx[2][8];
#pragma unroll
        for (int nt = 0; nt < 2; ++nt) {
            uint32_t o0 = SW128((wpix0 + nt * 8 + brow) * 128 + bcol);
            uint32_t o1 = SW128((wpix0 + nt * 8 + brow) * 128 + 64 + bcol);
            ldsm4(bx[nt], xtb + o0); ldsm4(bx[nt] + 4, xtb + o1);
        }
#pragma unroll
        for (int mt = 0; mt < 4; ++mt) {
            uint32_t aw[4][4];
            int ar = mt * 16 + (lane & 7) + ((lane >> 3) & 1) * 8;
#pragma unroll
            for (int kc = 0; kc < 4; ++kc)
                ldsm4(aw[kc], wtb + 16384 + SW128(ar * 128 + kc * 32 + acolb));
#pragma unroll
            for (int nt = 0; nt < 2; ++nt)
#pragma unroll
                for (int kc = 0; kc < 4; ++kc)
                    mma16816(chh[mt][nt], aw[kc], &bx[nt][kc * 2]);
        }
    }

    // epilogue
    int q = wpix0 + (lane >> 2);
    size_t fbase = (size_t)b * NPIX * HCH + (size_t)(n0 + q) * HCH;
#pragma unroll
    for (int nt = 0; nt < 8; ++nt) {
        int d = nt * 8 + (lane & 3) * 2;
        float b0 = bias_s[d], b1 = bias_s[d + 1];
        *(uint32_t*)&g_fT[fbase + d] =
            pack_h2(__float2half_rn(cf[nt][0] + b0), __float2half_rn(cf[nt][1] + b1));
        *(uint32_t*)&g_fT[fbase + 8 * HCH + d] =
            pack_h2(__float2half_rn(cf[nt][2] + b0), __float2half_rn(cf[nt][3] + b1));
        float c0g = bias_s[64 + d], c1g = bias_s[64 + d + 1];
        *(uint32_t*)&g_gT[fbase + d] =
            pack_h2(__float2half_rn(cg[nt][0] + c0g), __float2half_rn(cg[nt][1] + c1g));
        *(uint32_t*)&g_gT[fbase + 8 * HCH + d] =
            pack_h2(__float2half_rn(cg[nt][2] + c0g), __float2half_rn(cg[nt][3] + c1g));
    }
    __half* Hp = g_h + (size_t)b * HCH * NPIX;
#pragma unroll
    for (int mt = 0; mt < 4; ++mt) {
        int d0 = mt * 16 + (lane >> 2), d1 = d0 + 8;
        float bb0 = bias_s[128 + d0], bb1 = bias_s[128 + d1];
#pragma unroll
        for (int nt = 0; nt < 2; ++nt) {
            int pix = n0 + wpix0 + nt * 8 + (lane & 3) * 2;
            *(uint32_t*)&Hp[(size_t)d0 * NPIX + pix] =
                pack_h2(__float2half_rn(chh[mt][nt][0] + bb0), __float2half_rn(chh[mt][nt][1] + bb0));
            *(uint32_t*)&Hp[(size_t)d1 * NPIX + pix] =
                pack_h2(__float2half_rn(chh[mt][nt][2] + bb1), __float2half_rn(chh[mt][nt][3] + bb1));
        }
    }
}

// ---------------------------------------------------------------------------
// mma.sync (fp16) flash attention.  grid (32, B), 256 threads (8 warps x 16 q).
// 4 G/H buffers -> ONE barrier per tile (prefetch target was last read at
// iteration kt-1, ordered by this iteration's top barrier).
// SMEM: fT 16KB @0; 4 bufs {g 8KB, h 8KB} @16384.
// ---------------------------------------------------------------------------
#define SM_FH 0
#define SM_BUF 16384
#define SM_ATTN_TOT 81920

__global__ void __launch_bounds__(256, 1) attn_kernel()
{
    extern __shared__ __align__(128) char smem[];
    int tid = threadIdx.x;
    int lane = tid & 31, wid = tid >> 5;
    int m0 = wid * 16;
    int b = blockIdx.y, n0 = blockIdx.x * 128;
    uint32_t sb = smem_u32(smem);

    size_t bo = (size_t)b * NPIX * HCH;
    const __half* fT = g_fT + bo + (size_t)n0 * HCH;
    const __half* gT = g_gT + bo;
    const __half* hp = g_h + (size_t)b * HCH * NPIX;

    // prologue: tiles 0,1,2 into bufs 0,1,2 (fT rides with group 0)
    cp_tile(sb + SM_FH, fT, 64, tid, 128);
    cp_tile(sb + SM_BUF,        gT, 64, tid, 64);
    cp_tile(sb + SM_BUF + 8192, hp, NPIX, tid, 64);
    CP_COMMIT();
    cp_tile(sb + SM_BUF + 16384, gT + 64 * 64, 64, tid, 64);
    cp_tile(sb + SM_BUF + 24576, hp + 64, NPIX, tid, 64);
    CP_COMMIT();
    cp_tile(sb + SM_BUF + 32768, gT + 2 * 64 * 64, 64, tid, 64);
    cp_tile(sb + SM_BUF + 40960, hp + 128, NPIX, tid, 64);
    CP_COMMIT();

    CP_WAIT(2);
    __syncthreads();

    uint32_t fa[4][4];
    {
        int arow = m0 + (lane & 7) + ((lane >> 3) & 1) * 8;
        int acol = ((lane >> 4) & 1) * 16;
#pragma unroll
        for (int kc = 0; kc < 4; ++kc)
            ldsm4(fa[kc], sb + SM_FH + SW128(arow * 128 + kc * 32 + acol));
    }

    float oaccv[32];
#pragma unroll
    for (int i = 0; i < 32; ++i) oaccv[i] = 0.f;
    float m0r = -1e30f, m1r = -1e30f, l0 = 0.f, l1 = 0.f;

    int brow = lane & 7;
    int bj = lane >> 3;
    int bcol = (bj & 1) * 16 + (bj >> 1) * 32;

    for (int kt = 0; kt < 64; ++kt) {
        if (kt > 0) { CP_WAIT(2); __syncthreads(); }
        // prefetch tile kt+3 into buf (kt+3)&3 (last read at iter kt-1; safe after barrier)
        if (kt < 61) {
            uint32_t bb = sb + SM_BUF + ((kt + 3) & 3) * 16384;
            cp_tile(bb,        gT + (size_t)(kt + 3) * 64 * 64, 64, tid, 64);
            cp_tile(bb + 8192, hp + (kt + 3) * 64, NPIX, tid, 64);
            CP_COMMIT();
        }
        uint32_t gB = sb + SM_BUF + (kt & 3) * 16384;
        uint32_t hB = gB + 8192;

        float s[32];
#pragma unroll
        for (int i = 0; i < 32; ++i) s[i] = 0.f;
#pragma unroll
        for (int nt = 0; nt < 8; ++nt) {
            uint32_t bfr[8];
            uint32_t o0 = SW128((nt * 8 + brow) * 128 + 0 + bcol);
            uint32_t o1 = SW128((nt * 8 + brow) * 128 + 64 + bcol);
            ldsm4(bfr,     gB + o0);
            ldsm4(bfr + 4, gB + o1);
            float* s4 = &s[nt * 4];
#pragma unroll
            for (int kc = 0; kc < 4; ++kc) mma16816(s4, fa[kc], &bfr[kc * 2]);
        }

        float mx0 = -1e30f, mx1 = -1e30f;
#pragma unroll
        for (int nt = 0; nt < 8; ++nt) {
            mx0 = fmaxf(mx0, fmaxf(s[nt * 4 + 0], s[nt * 4 + 1]));
            mx1 = fmaxf(mx1, fmaxf(s[nt * 4 + 2], s[nt * 4 + 3]));
        }
        mx0 = fmaxf(mx0, __shfl_xor_sync(0xffffffffu, mx0, 1));
        mx0 = fmaxf(mx0, __shfl_xor_sync(0xffffffffu, mx0, 2));
        mx1 = fmaxf(mx1, __shfl_xor_sync(0xffffffffu, mx1, 1));
        mx1 = fmaxf(mx1, __shfl_xor_sync(0xffffffffu, mx1, 2));
        float mn0 = fmaxf(m0r, mx0), mn1 = fmaxf(m1r, mx1);
        float c0 = ex2(m0r - mn0), c1 = ex2(m1r - mn1);
        m0r = mn0; m1r = mn1;
        float ls0 = 0.f, ls1 = 0.f;
#pragma unroll
        for (int nt = 0; nt < 8; ++nt) {
            float p0 = ex2(s[nt * 4 + 0] - mn0);
            float p1 = ex2(s[nt * 4 + 1] - mn0);
            float p2 = ex2(s[nt * 4 + 2] - mn1);
            float p3 = ex2(s[nt * 4 + 3] - mn1);
            s[nt * 4 + 0] = p0; s[nt * 4 + 1] = p1;
            s[nt * 4 + 2] = p2; s[nt * 4 + 3] = p3;
            ls0 += p0 + p1; ls1 += p2 + p3;
        }
        l0 = l0 * c0 + ls0;
        l1 = l1 * c1 + ls1;
#pragma unroll
        for (int nt = 0; nt < 8; ++nt) {
            oaccv[nt * 4 + 0] *= c0; oaccv[nt * 4 + 1] *= c0;
            oaccv[nt * 4 + 2] *= c1; oaccv[nt * 4 + 3] *= c1;
        }

        uint32_t pa[4][4];
#pragma unroll
        for (int j = 0; j < 4; ++j) {
            float* sa = &s[(2 * j) * 4];
            float* sc = &s[(2 * j + 1) * 4];
            pa[j][0] = pack_h2(__float2half_rn(sa[0]), __float2half_rn(sa[1]));
            pa[j][1] = pack_h2(__float2half_rn(sa[2]), __float2half_rn(sa[3]));
            pa[j][2] = pack_h2(__float2half_rn(sc[0]), __float2half_rn(sc[1]));
            pa[j][3] = pack_h2(__float2half_rn(sc[2]), __float2half_rn(sc[3]));
        }

#pragma unroll
        for (int nd = 0; nd < 8; ++nd) {
            uint32_t bfr[8];
            uint32_t o0 = SW128((nd * 8 + brow) * 128 + 0 + bcol);
            uint32_t o1 = SW128((nd * 8 + brow) * 128 + 64 + bcol);
            ldsm4(bfr,     hB + o0);
            ldsm4(bfr + 4, hB + o1);
            float* o4 = &oaccv[nd * 4];
#pragma unroll
            for (int j = 0; j < 4; ++j) mma16816(o4, pa[j], &bfr[j * 2]);
        }
    }

    // epilogue: write o^T fp16 [pix][64] directly from fragments
    l0 += __shfl_xor_sync(0xffffffffu, l0, 1);
    l0 += __shfl_xor_sync(0xffffffffu, l0, 2);
    l1 += __shfl_xor_sync(0xffffffffu, l1, 1);
    l1 += __shfl_xor_sync(0xffffffffu, l1, 2);
    float inv0 = 1.f / l0, inv1 = 1.f / l1;

    int q0 = m0 + (lane >> 2), q1 = q0 + 8;
    size_t r0 = (size_t)b * NPIX * HCH + (size_t)(n0 + q0) * HCH;
    size_t r1 = (size_t)b * NPIX * HCH + (size_t)(n0 + q1) * HCH;
#pragma unroll
    for (int nt = 0; nt < 8; ++nt) {
        int d = nt * 8 + (lane & 3) * 2;
        *(uint32_t*)&g_oT[r0 + d] = pack_h2(__float2half_rn(oaccv[nt * 4 + 0] * inv0),
                                            __float2half_rn(oaccv[nt * 4 + 1] * inv0));
        *(uint32_t*)&g_oT[r1 + d] = pack_h2(__float2half_rn(oaccv[nt * 4 + 2] * inv1),
                                            __float2half_rn(oaccv[nt * 4 + 3] * inv1));
    }
}

// ---------------------------------------------------------------------------
// MMA outproj: out = gamma*(Wv' @ o + bv) + x.  grid (32, 8, 4), 256 threads.
// ---------------------------------------------------------------------------
__global__ void __launch_bounds__(256) outproj_kernel(
    const float* __restrict__ x, const float* __restrict__ bv,
    const float* __restrict__ gamma, float* __restrict__ out)
{
    __shared__ __align__(1024) char osm[24576];   // Wv tile 8KB @0, oT tile 16KB @8192
    int tid = threadIdx.x;
    int lane = tid & 31, wid = tid >> 5;
    int wpix0 = wid * 16;
    int nb = blockIdx.x, ct = blockIdx.y, b = blockIdx.z;
    int n0 = nb * 128, c0 = ct * 64;
    uint32_t sb = smem_u32(osm);

    cp_tile(sb, g_Wvp + c0 * 64, 64, tid, 64);
    cp_tile(sb + 8192, g_oT + ((size_t)b * NPIX + n0) * 64, 64, tid, 128);
    CP_COMMIT();
    CP_WAIT(0);
    __syncthreads();

    int brow = lane & 7;
    int bj = lane >> 3;
    int bcol = (bj & 1) * 16 + (bj >> 1) * 32;
    int acolb = ((lane >> 4) & 1) * 16;

    float co[4][2][4];
#pragma unroll
    for (int i = 0; i < 4; ++i)
#pragma unroll
        for (int n = 0; n < 2; ++n)
#pragma unroll
            for (int j = 0; j < 4; ++j) co[i][n][j] = 0.f;

    uint32_t bx[2][8];
#pragma unroll
    for (int nt = 0; nt < 2; ++nt) {
        uint32_t o0 = SW128((wpix0 + nt * 8 + brow) * 128 + bcol);
        uint32_t o1 = SW128((wpix0 + nt * 8 + brow) * 128 + 64 + bcol);
        ldsm4(bx[nt], sb + 8192 + o0); ldsm4(bx[nt] + 4, sb + 8192 + o1);
    }
#pragma unroll
    for (int mt = 0; mt < 4; ++mt) {
        uint32_t aw[4][4];
        int ar = mt * 16 + (lane & 7) + ((lane >> 3) & 1) * 8;
#pragma unroll
        for (int kc = 0; kc < 4; ++kc)
            ldsm4(aw[kc], sb + SW128(ar * 128 + kc * 32 + acolb));
#pragma unroll
        for (int nt = 0; nt < 2; ++nt)
#pragma unroll
            for (int kc = 0; kc < 4; ++kc)
                mma16816(co[mt][nt], aw[kc], &bx[nt][kc * 2]);
    }

    float gm = gamma[0];
#pragma unroll
    for (int mt = 0; mt < 4; ++mt) {
        int cA = c0 + mt * 16 + (lane >> 2);
        int cB = cA + 8;
        float bA = bv[cA], bB = bv[cB];
#pragma unroll
        for (int nt = 0; nt < 2; ++nt) {
            int pix = n0 + wpix0 + nt * 8 + (lane & 3) * 2;
            size_t iA = ((size_t)b * CCH + cA) * NPIX + pix;
            size_t iB = ((size_t)b * CCH + cB) * NPIX + pix;
            float2 xA = *(const float2*)&x[iA];
            float2 xB = *(const float2*)&x[iB];
            float2 oA, oB;
            oA.x = gm * (co[mt][nt][0] + bA) + xA.x;
            oA.y = gm * (co[mt][nt][1] + bA) + xA.y;
            oB.x = gm * (co[mt][nt][2] + bB) + xB.x;
            oB.y = gm * (co[mt][nt][3] + bB) + xB.y;
            *(float2*)&out[iA] = oA;
            *(float2*)&out[iB] = oB;
        }
    }
}

// ---------------------------------------------------------------------------
extern "C" void kernel_launch(void* const* d_in, const int* in_sizes, int n_in,
                              void* d_out, int out_size)
{
    const float* x     = (const float*)d_in[0];
    const float* Wf    = (const float*)d_in[1];
    const float* bf    = (const float*)d_in[2];
    const float* Wg    = (const float*)d_in[3];
    const float* bg    = (const float*)d_in[4];
    const float* Wh    = (const float*)d_in[5];
    const float* bh    = (const float*)d_in[6];
    const float* Wv    = (const float*)d_in[7];
    const float* bv    = (const float*)d_in[8];
    const float* uf    = (const float*)d_in[9];
    const float* ug    = (const float*)d_in[10];
    const float* uh    = (const float*)d_in[11];
    const float* uv    = (const float*)d_in[12];
    const float* gamma = (const float*)d_in[13];
    float* out = (float*)d_out;

    cudaFuncSetAttribute(attn_kernel, cudaFuncAttributeMaxDynamicSharedMemorySize, SM_ATTN_TOT);
    cudaFuncSetAttribute(proj_kernel, cudaFuncAttributeMaxDynamicSharedMemorySize, SM_PROJ_TOT);

    spectral_kernel<<<4, 512>>>(Wf, Wg, Wh, Wv, uf, ug, uh, uv);
    wconv_kernel<<<128, 256>>>(Wf, Wg, Wh, Wv);
    proj_kernel<<<dim3(NPIX / 128, BATCH), 256, SM_PROJ_TOT>>>(x, bf, bg, bh);
    attn_kernel<<<dim3(NPIX / 128, BATCH), 256, SM_ATTN_TOT>>>();
    outproj_kernel<<<dim3(NPIX / 128, CCH / 64, BATCH), 256>>>(x, bv, gamma, out);
}